// round 1
// baseline (speedup 1.0000x reference)
#include <cuda_runtime.h>
#include <cuda_bf16.h>
#include <math.h>

// ---------------- problem-size constants (fixed dataset) ----------------
#define NMAX   50000
#define EMAX   300000
#define Dm     128
#define Hh     8
#define DHd    16

// ---------------- scratch (static device memory; no allocations) --------
__device__ float g_xn  [NMAX * Dm];
__device__ float g_q   [NMAX * Dm];
__device__ float g_kf  [NMAX * Dm];
__device__ float g_vf  [NMAX * Dm];
__device__ float g_kg  [NMAX * Dm];
__device__ float g_vg  [NMAX * Dm];
__device__ float g_gact[NMAX * Dm];
__device__ float g_x1  [NMAX * Dm];
__device__ float g_xn2 [NMAX * Dm];
__device__ float g_hid [NMAX * 4 * Dm];
__device__ float g_Wbig[Dm * 640];
__device__ float g_bbig[640];
__device__ int   g_count [NMAX];
__device__ int   g_offs  [NMAX + 1];
__device__ int   g_cursor[NMAX];
__device__ int   g_entries[2 * EMAX];

__device__ __forceinline__ float gelu_exact(float v) {
    return v * 0.5f * (1.0f + erff(v * 0.70710678118654752440f));
}

// ---------------- LayerNorm: one warp per row (128 cols) ----------------
// WHICH==0: in = param x, out = g_xn.  WHICH==1: in = g_x1, out = g_xn2.
template <int WHICH>
__global__ void ln_kernel(const float* __restrict__ xin,
                          const float* __restrict__ g,
                          const float* __restrict__ b, int N)
{
    int warp = (blockIdx.x * blockDim.x + threadIdx.x) >> 5;
    int lane = threadIdx.x & 31;
    if (warp >= N) return;
    const float* in = (WHICH == 0) ? xin : g_x1;
    float*       out = (WHICH == 0) ? g_xn : g_xn2;
    float4 v = *reinterpret_cast<const float4*>(in + (size_t)warp * Dm + lane * 4);
    float s = v.x + v.y + v.z + v.w;
    #pragma unroll
    for (int o = 16; o; o >>= 1) s += __shfl_xor_sync(0xffffffffu, s, o);
    float mu = s * (1.0f / 128.0f);
    float dx = v.x - mu, dy = v.y - mu, dz = v.z - mu, dw = v.w - mu;
    float s2 = dx * dx + dy * dy + dz * dz + dw * dw;
    #pragma unroll
    for (int o = 16; o; o >>= 1) s2 += __shfl_xor_sync(0xffffffffu, s2, o);
    float r = rsqrtf(s2 * (1.0f / 128.0f) + 1e-5f);
    float4 gg = *reinterpret_cast<const float4*>(g + lane * 4);
    float4 bb = *reinterpret_cast<const float4*>(b + lane * 4);
    float4 o4 = make_float4(dx * r * gg.x + bb.x, dy * r * gg.y + bb.y,
                            dz * r * gg.z + bb.z, dw * r * gg.w + bb.w);
    *reinterpret_cast<float4*>(out + (size_t)warp * Dm + lane * 4) = o4;
}

// ---------- fold per-head relation matrices into projection weights ------
// Wbig[128 x 640] row-major (k-major): cols [0:128)=Wq, [128:256)=Wkf*p_f/4,
// [256:384)=Wvf, [384:512)=Wkg*p_g/4, [512:640)=Wvg. Bias likewise.
__global__ void prep_w_kernel(const float* __restrict__ kqv_w,
                              const float* __restrict__ kqv_b,
                              const float* __restrict__ a_f,
                              const float* __restrict__ m_f,
                              const float* __restrict__ p_f,
                              const float* __restrict__ a_g,
                              const float* __restrict__ m_g,
                              const float* __restrict__ p_g)
{
    int idx = blockIdx.x * blockDim.x + threadIdx.x;
    if (idx >= Dm * 640) return;
    int n = idx % 640;
    int k = idx / 640;
    float val;
    if (n < 128) {
        val = kqv_w[k * 384 + 128 + n];         // q block
        if (k == 0) g_bbig[n] = kqv_b[128 + n];
    } else {
        int gsel = (n - 128) >> 7;              // 0:kf 1:vf 2:kg 3:vg
        int c = (n - 128) & 127;
        int h = c >> 4, f = c & 15;
        const float* mat; int srcoff; float scale = 1.0f;
        if      (gsel == 0) { mat = a_f; srcoff = 0;   scale = p_f[h] * 0.25f; }
        else if (gsel == 1) { mat = m_f; srcoff = 256; }
        else if (gsel == 2) { mat = a_g; srcoff = 0;   scale = p_g[h] * 0.25f; }
        else                { mat = m_g; srcoff = 256; }
        float s = 0.0f, bs = 0.0f;
        #pragma unroll
        for (int d = 0; d < 16; d++) {
            float w = mat[h * 256 + d * 16 + f];
            s  += kqv_w[k * 384 + srcoff + h * 16 + d] * w;
            bs += kqv_b[srcoff + h * 16 + d] * w;
        }
        val = s * scale;
        if (k == 0) g_bbig[n] = bs * scale;
    }
    g_Wbig[k * 640 + n] = val;
}

// ---------------- CSR build: count / scan / scatter ---------------------
__global__ void zero_count_kernel(int N)
{
    int i = blockIdx.x * blockDim.x + threadIdx.x;
    if (i < N) g_count[i] = 0;
}

__global__ void count_kernel(const int* __restrict__ ef,
                             const int* __restrict__ eg, int E)
{
    int i = blockIdx.x * blockDim.x + threadIdx.x;
    if (i >= 2 * E) return;
    int dst = (i < E) ? ef[E + i] : eg[E + (i - E)];
    atomicAdd(&g_count[dst], 1);
}

__global__ void scan_kernel(int N)
{
    __shared__ int sm[1024];
    int t = threadIdx.x;
    int chunk = (N + 1023) >> 10;
    int b0 = t * chunk;
    int b1 = min(b0 + chunk, N);
    int s = 0;
    for (int i = b0; i < b1; i++) s += g_count[i];
    sm[t] = s;
    __syncthreads();
    for (int off = 1; off < 1024; off <<= 1) {
        int v = (t >= off) ? sm[t - off] : 0;
        __syncthreads();
        sm[t] += v;
        __syncthreads();
    }
    int run = sm[t] - s;    // exclusive prefix
    for (int i = b0; i < b1; i++) {
        g_offs[i] = run;
        g_cursor[i] = run;
        run += g_count[i];
    }
    if (t == 1023) g_offs[N] = sm[1023];
}

__global__ void scatter_kernel(const int* __restrict__ ef,
                               const int* __restrict__ eg, int E)
{
    int i = blockIdx.x * blockDim.x + threadIdx.x;
    if (i >= 2 * E) return;
    int src, dst, tbit;
    if (i < E) { src = ef[i];       dst = ef[E + i];       tbit = 0; }
    else       { int j = i - E; src = eg[j]; dst = eg[E + j]; tbit = 1 << 16; }
    int pos = atomicAdd(&g_cursor[dst], 1);
    g_entries[pos] = src | tbit;
}

// ------------- fused segment-softmax + aggregation + GELU ---------------
// One warp per destination node. Lane l owns head h = l>>2, dims (l&3)*4..+3.
// Single pass: denom = sum exp(l_e), acc = sum exp(l_e)*v_rel (max-free is
// numerically safe: logit std ~0.06).
__global__ void agg_kernel(int N)
{
    int warp = (blockIdx.x * blockDim.x + threadIdx.x) >> 5;
    int lane = threadIdx.x & 31;
    if (warp >= N) return;
    float4 q4 = *reinterpret_cast<const float4*>(g_q + (size_t)warp * Dm + lane * 4);
    float4 acc = make_float4(0.f, 0.f, 0.f, 0.f);
    float denom = 0.0f;
    int beg = g_offs[warp], end = g_offs[warp + 1];
    for (int j = beg; j < end; j++) {
        int e   = g_entries[j];
        int src = e & 0xFFFF;
        const float* kp = (e & 0x10000) ? g_kg : g_kf;
        const float* vp = (e & 0x10000) ? g_vg : g_vf;
        float4 k4 = *reinterpret_cast<const float4*>(kp + (size_t)src * Dm + lane * 4);
        float p = q4.x * k4.x + q4.y * k4.y + q4.z * k4.z + q4.w * k4.w;
        p += __shfl_xor_sync(0xffffffffu, p, 1);
        p += __shfl_xor_sync(0xffffffffu, p, 2);   // full per-head logit (p/sqrt(dh) pre-folded)
        float w = __expf(p);
        denom += w;
        float4 v4 = *reinterpret_cast<const float4*>(vp + (size_t)src * Dm + lane * 4);
        acc.x += w * v4.x; acc.y += w * v4.y; acc.z += w * v4.z; acc.w += w * v4.w;
    }
    float rd = 1.0f / (denom + 1e-16f);
    float4 o4 = make_float4(gelu_exact(acc.x * rd), gelu_exact(acc.y * rd),
                            gelu_exact(acc.z * rd), gelu_exact(acc.w * rd));
    *reinterpret_cast<float4*>(g_gact + (size_t)warp * Dm + lane * 4) = o4;
}

// ---------------- tiled fp32 GEMM, 128x128 tile, 8x8 per thread ---------
// MODE 0: g_xn @ g_Wbig  -> {g_q,g_kf,g_vf,g_kg,g_vg} (+bbig)  K=128 NT=640
// MODE 1: g_gact @ out_w -> g_x1 = x + sig*(C+out_b) + (1-sig)*g_xn
// MODE 2: g_xn2 @ w1     -> g_hid = gelu(C + b1)               K=128 NT=512
// MODE 3: g_hid @ w2     -> out   = g_x1 + C + b2              K=512 NT=128
#define BM 128
#define BN 128
#define BKg 8

template <int MODE, int K, int NT>
__global__ __launch_bounds__(256, 2)
void gemm_kernel(const float* __restrict__ Bext,
                 const float* __restrict__ bias,
                 const float* __restrict__ aux,    // MODE1: x
                 const float* __restrict__ skip,   // MODE1 only
                 float* __restrict__ outp,         // MODE3: d_out
                 int M)
{
    __shared__ float As[BKg][BM + 4];
    __shared__ float Bs[BKg][BN + 4];
    const float* A;
    const float* B;
    if      (MODE == 0) { A = g_xn;   B = g_Wbig; }
    else if (MODE == 1) { A = g_gact; B = Bext; }
    else if (MODE == 2) { A = g_xn2;  B = Bext; }
    else                { A = g_hid;  B = Bext; }

    int tid = threadIdx.x;
    int m0 = blockIdx.x * BM;
    int n0 = blockIdx.y * BN;
    int tx = tid & 15, ty = tid >> 4;
    int arow = tid >> 1, akq = (tid & 1) * 4;
    int brow = tid >> 5, bcol = (tid & 31) * 4;

    float acc[8][8];
    #pragma unroll
    for (int i = 0; i < 8; i++)
        #pragma unroll
        for (int j = 0; j < 8; j++) acc[i][j] = 0.0f;

    for (int k0 = 0; k0 < K; k0 += BKg) {
        float4 av = make_float4(0.f, 0.f, 0.f, 0.f);
        int gm = m0 + arow;
        if (gm < M)
            av = *reinterpret_cast<const float4*>(A + (size_t)gm * K + k0 + akq);
        As[akq + 0][arow] = av.x;
        As[akq + 1][arow] = av.y;
        As[akq + 2][arow] = av.z;
        As[akq + 3][arow] = av.w;
        float4 bv = *reinterpret_cast<const float4*>(B + (size_t)(k0 + brow) * NT + n0 + bcol);
        *reinterpret_cast<float4*>(&Bs[brow][bcol]) = bv;
        __syncthreads();
        #pragma unroll
        for (int k = 0; k < BKg; k++) {
            float4 a0 = *reinterpret_cast<const float4*>(&As[k][ty * 8]);
            float4 a1 = *reinterpret_cast<const float4*>(&As[k][ty * 8 + 4]);
            float4 b0 = *reinterpret_cast<const float4*>(&Bs[k][tx * 8]);
            float4 b1 = *reinterpret_cast<const float4*>(&Bs[k][tx * 8 + 4]);
            float ar[8] = {a0.x, a0.y, a0.z, a0.w, a1.x, a1.y, a1.z, a1.w};
            float br[8] = {b0.x, b0.y, b0.z, b0.w, b1.x, b1.y, b1.z, b1.w};
            #pragma unroll
            for (int i = 0; i < 8; i++)
                #pragma unroll
                for (int j = 0; j < 8; j++)
                    acc[i][j] += ar[i] * br[j];
        }
        __syncthreads();
    }

    // ----------------- epilogues -----------------
    float sig = 0.0f;
    if (MODE == 1) sig = 1.0f / (1.0f + __expf(-skip[0]));

    float* Cp = nullptr;
    if (MODE == 0) {
        switch (blockIdx.y) {
            case 0: Cp = g_q;  break;
            case 1: Cp = g_kf; break;
            case 2: Cp = g_vf; break;
            case 3: Cp = g_kg; break;
            default: Cp = g_vg; break;
        }
    }

    #pragma unroll
    for (int i = 0; i < 8; i++) {
        int gm = m0 + ty * 8 + i;
        if (gm >= M) continue;
        #pragma unroll
        for (int j = 0; j < 8; j++) {
            int gn = n0 + tx * 8 + j;       // global output column in [0,NT)
            float v = acc[i][j];
            if (MODE == 0) {
                v += g_bbig[gn];
                Cp[(size_t)gm * Dm + (tx * 8 + j)] = v;
            } else if (MODE == 1) {
                v += bias[gn];
                float xv  = aux[(size_t)gm * Dm + gn];
                float xnv = g_xn[(size_t)gm * Dm + gn];
                g_x1[(size_t)gm * Dm + gn] = xv + sig * v + (1.0f - sig) * xnv;
            } else if (MODE == 2) {
                v += bias[gn];
                g_hid[(size_t)gm * (4 * Dm) + gn] = gelu_exact(v);
            } else {
                v += bias[gn];
                outp[(size_t)gm * Dm + gn] = g_x1[(size_t)gm * Dm + gn] + v;
            }
        }
    }
}

// ------------------------------- launch ---------------------------------
extern "C" void kernel_launch(void* const* d_in, const int* in_sizes, int n_in,
                              void* d_out, int out_size)
{
    const float* x      = (const float*)d_in[0];
    const int*   ef     = (const int*)  d_in[1];
    const int*   eg     = (const int*)  d_in[2];
    const float* kqv_w  = (const float*)d_in[3];
    const float* kqv_b  = (const float*)d_in[4];
    const float* a_f    = (const float*)d_in[5];
    const float* m_f    = (const float*)d_in[6];
    const float* p_f    = (const float*)d_in[7];
    const float* a_g    = (const float*)d_in[8];
    const float* m_g    = (const float*)d_in[9];
    const float* p_g    = (const float*)d_in[10];
    const float* out_w  = (const float*)d_in[11];
    const float* out_b  = (const float*)d_in[12];
    const float* skip   = (const float*)d_in[13];
    const float* ln1_g  = (const float*)d_in[14];
    const float* ln1_b  = (const float*)d_in[15];
    const float* ln2_g  = (const float*)d_in[16];
    const float* ln2_b  = (const float*)d_in[17];
    const float* w1     = (const float*)d_in[18];
    const float* b1     = (const float*)d_in[19];
    const float* w2     = (const float*)d_in[20];
    const float* b2     = (const float*)d_in[21];
    float* out = (float*)d_out;

    int N = in_sizes[0] / Dm;
    int E = in_sizes[1] / 2;
    if (N > NMAX) N = NMAX;
    if (E > EMAX) E = EMAX;

    int mtiles = (N + BM - 1) / BM;

    // 1. LN1: x -> g_xn
    ln_kernel<0><<<(N + 7) / 8, 256>>>(x, ln1_g, ln1_b, N);
    // 2. fold relation matrices into Wbig/bbig
    prep_w_kernel<<<(Dm * 640 + 255) / 256, 256>>>(kqv_w, kqv_b, a_f, m_f, p_f,
                                                   a_g, m_g, p_g);
    // 3. fused projection: q,kf,vf,kg,vg
    gemm_kernel<0, 128, 640><<<dim3(mtiles, 5), 256>>>(nullptr, nullptr, nullptr,
                                                       nullptr, nullptr, N);
    // 4-7. CSR build by dst
    zero_count_kernel<<<(N + 255) / 256, 256>>>(N);
    count_kernel<<<(2 * E + 255) / 256, 256>>>(ef, eg, E);
    scan_kernel<<<1, 1024>>>(N);
    scatter_kernel<<<(2 * E + 255) / 256, 256>>>(ef, eg, E);
    // 8. fused softmax + aggregation + gelu
    agg_kernel<<<(N + 7) / 8, 256>>>(N);
    // 9. out projection + skip-mix + residual -> g_x1
    gemm_kernel<1, 128, 128><<<dim3(mtiles, 1), 256>>>(out_w, out_b, x, skip,
                                                       nullptr, N);
    // 10. LN2: g_x1 -> g_xn2
    ln_kernel<1><<<(N + 7) / 8, 256>>>(nullptr, ln2_g, ln2_b, N);
    // 11. FFN up + gelu
    gemm_kernel<2, 128, 512><<<dim3(mtiles, 4), 256>>>(w1, b1, nullptr, nullptr,
                                                       nullptr, N);
    // 12. FFN down + residual -> out
    gemm_kernel<3, 512, 128><<<dim3(mtiles, 1), 256>>>(w2, b2, nullptr, nullptr,
                                                       out, N);
}

// round 2
// speedup vs baseline: 1.1563x; 1.1563x over previous
#include <cuda_runtime.h>
#include <cuda_bf16.h>
#include <math.h>

// ---------------- problem-size constants (fixed dataset) ----------------
#define NMAX   50000
#define EMAX   300000
#define Dm     128
#define Hh     8
#define DHd    16

// ---------------- scratch (static device memory; no allocations) --------
__device__ float g_xn  [NMAX * Dm];
__device__ float g_q   [NMAX * Dm];
__device__ float g_kf  [NMAX * Dm];
__device__ float g_vf  [NMAX * Dm];
__device__ float g_kg  [NMAX * Dm];
__device__ float g_vg  [NMAX * Dm];
__device__ float g_gact[NMAX * Dm];
__device__ float g_x1  [NMAX * Dm];
__device__ float g_xn2 [NMAX * Dm];
__device__ float g_hid [NMAX * 4 * Dm];
__device__ float g_Wbig[Dm * 640];
__device__ float g_bbig[640];
__device__ int   g_count [NMAX];
__device__ int   g_offs  [NMAX + 1];
__device__ int   g_cursor[NMAX];
__device__ int   g_entries[2 * EMAX];

typedef unsigned long long u64;

__device__ __forceinline__ float gelu_exact(float v) {
    return v * 0.5f * (1.0f + erff(v * 0.70710678118654752440f));
}

// packed f32x2 helpers (FFMA2 on sm_103a)
__device__ __forceinline__ u64 packf2(float lo, float hi) {
    u64 r; asm("mov.b64 %0, {%1, %2};" : "=l"(r) : "f"(lo), "f"(hi)); return r;
}
__device__ __forceinline__ u64 dupf2(float a) {
    u64 r; asm("mov.b64 %0, {%1, %1};" : "=l"(r) : "f"(a)); return r;
}
__device__ __forceinline__ void ffma2(u64& d, u64 a, u64 b) {
    asm("fma.rn.f32x2 %0, %1, %2, %0;" : "+l"(d) : "l"(a), "l"(b));
}

// ---------------- LayerNorm: one warp per row (128 cols) ----------------
template <int WHICH>
__global__ void ln_kernel(const float* __restrict__ xin,
                          const float* __restrict__ g,
                          const float* __restrict__ b, int N)
{
    int warp = (blockIdx.x * blockDim.x + threadIdx.x) >> 5;
    int lane = threadIdx.x & 31;
    if (warp >= N) return;
    const float* in = (WHICH == 0) ? xin : g_x1;
    float*       out = (WHICH == 0) ? g_xn : g_xn2;
    float4 v = *reinterpret_cast<const float4*>(in + (size_t)warp * Dm + lane * 4);
    float s = v.x + v.y + v.z + v.w;
    #pragma unroll
    for (int o = 16; o; o >>= 1) s += __shfl_xor_sync(0xffffffffu, s, o);
    float mu = s * (1.0f / 128.0f);
    float dx = v.x - mu, dy = v.y - mu, dz = v.z - mu, dw = v.w - mu;
    float s2 = dx * dx + dy * dy + dz * dz + dw * dw;
    #pragma unroll
    for (int o = 16; o; o >>= 1) s2 += __shfl_xor_sync(0xffffffffu, s2, o);
    float r = rsqrtf(s2 * (1.0f / 128.0f) + 1e-5f);
    float4 gg = *reinterpret_cast<const float4*>(g + lane * 4);
    float4 bb = *reinterpret_cast<const float4*>(b + lane * 4);
    float4 o4 = make_float4(dx * r * gg.x + bb.x, dy * r * gg.y + bb.y,
                            dz * r * gg.z + bb.z, dw * r * gg.w + bb.w);
    *reinterpret_cast<float4*>(out + (size_t)warp * Dm + lane * 4) = o4;
}

// ---------- fold per-head relation matrices into projection weights ------
__global__ void prep_w_kernel(const float* __restrict__ kqv_w,
                              const float* __restrict__ kqv_b,
                              const float* __restrict__ a_f,
                              const float* __restrict__ m_f,
                              const float* __restrict__ p_f,
                              const float* __restrict__ a_g,
                              const float* __restrict__ m_g,
                              const float* __restrict__ p_g)
{
    int idx = blockIdx.x * blockDim.x + threadIdx.x;
    if (idx >= Dm * 640) return;
    int n = idx % 640;
    int k = idx / 640;
    float val;
    if (n < 128) {
        val = kqv_w[k * 384 + 128 + n];         // q block
        if (k == 0) g_bbig[n] = kqv_b[128 + n];
    } else {
        int gsel = (n - 128) >> 7;              // 0:kf 1:vf 2:kg 3:vg
        int c = (n - 128) & 127;
        int h = c >> 4, f = c & 15;
        const float* mat; int srcoff; float scale = 1.0f;
        if      (gsel == 0) { mat = a_f; srcoff = 0;   scale = p_f[h] * 0.25f; }
        else if (gsel == 1) { mat = m_f; srcoff = 256; }
        else if (gsel == 2) { mat = a_g; srcoff = 0;   scale = p_g[h] * 0.25f; }
        else                { mat = m_g; srcoff = 256; }
        float s = 0.0f, bs = 0.0f;
        #pragma unroll
        for (int d = 0; d < 16; d++) {
            float w = mat[h * 256 + d * 16 + f];
            s  += kqv_w[k * 384 + srcoff + h * 16 + d] * w;
            bs += kqv_b[srcoff + h * 16 + d] * w;
        }
        val = s * scale;
        if (k == 0) g_bbig[n] = bs * scale;
    }
    g_Wbig[k * 640 + n] = val;
}

// ---------------- CSR build: count / scan / scatter ---------------------
__global__ void zero_count_kernel(int N)
{
    int i = blockIdx.x * blockDim.x + threadIdx.x;
    if (i < N) g_count[i] = 0;
}

__global__ void count_kernel(const int* __restrict__ ef,
                             const int* __restrict__ eg, int E)
{
    int i = blockIdx.x * blockDim.x + threadIdx.x;
    if (i >= 2 * E) return;
    int dst = (i < E) ? ef[E + i] : eg[E + (i - E)];
    atomicAdd(&g_count[dst], 1);
}

__global__ void scan_kernel(int N)
{
    __shared__ int sm[1024];
    int t = threadIdx.x;
    int chunk = (N + 1023) >> 10;
    int b0 = t * chunk;
    int b1 = min(b0 + chunk, N);
    int s = 0;
    for (int i = b0; i < b1; i++) s += g_count[i];
    sm[t] = s;
    __syncthreads();
    for (int off = 1; off < 1024; off <<= 1) {
        int v = (t >= off) ? sm[t - off] : 0;
        __syncthreads();
        sm[t] += v;
        __syncthreads();
    }
    int run = sm[t] - s;    // exclusive prefix
    for (int i = b0; i < b1; i++) {
        g_offs[i] = run;
        g_cursor[i] = run;
        run += g_count[i];
    }
    if (t == 1023) g_offs[N] = sm[1023];
}

__global__ void scatter_kernel(const int* __restrict__ ef,
                               const int* __restrict__ eg, int E)
{
    int i = blockIdx.x * blockDim.x + threadIdx.x;
    if (i >= 2 * E) return;
    int src, dst, tbit;
    if (i < E) { src = ef[i];       dst = ef[E + i];       tbit = 0; }
    else       { int j = i - E; src = eg[j]; dst = eg[E + j]; tbit = 1 << 16; }
    int pos = atomicAdd(&g_cursor[dst], 1);
    g_entries[pos] = src | tbit;
}

// ------------- fused segment-softmax + aggregation + GELU ---------------
__global__ void agg_kernel(int N)
{
    int warp = (blockIdx.x * blockDim.x + threadIdx.x) >> 5;
    int lane = threadIdx.x & 31;
    if (warp >= N) return;
    float4 q4 = *reinterpret_cast<const float4*>(g_q + (size_t)warp * Dm + lane * 4);
    float4 acc = make_float4(0.f, 0.f, 0.f, 0.f);
    float denom = 0.0f;
    int beg = g_offs[warp], end = g_offs[warp + 1];
    for (int j = beg; j < end; j++) {
        int e   = g_entries[j];
        int src = e & 0xFFFF;
        const float* kp = (e & 0x10000) ? g_kg : g_kf;
        const float* vp = (e & 0x10000) ? g_vg : g_vf;
        float4 k4 = *reinterpret_cast<const float4*>(kp + (size_t)src * Dm + lane * 4);
        float p = q4.x * k4.x + q4.y * k4.y + q4.z * k4.z + q4.w * k4.w;
        p += __shfl_xor_sync(0xffffffffu, p, 1);
        p += __shfl_xor_sync(0xffffffffu, p, 2);
        float w = __expf(p);
        denom += w;
        float4 v4 = *reinterpret_cast<const float4*>(vp + (size_t)src * Dm + lane * 4);
        acc.x += w * v4.x; acc.y += w * v4.y; acc.z += w * v4.z; acc.w += w * v4.w;
    }
    float rd = 1.0f / (denom + 1e-16f);
    float4 o4 = make_float4(gelu_exact(acc.x * rd), gelu_exact(acc.y * rd),
                            gelu_exact(acc.z * rd), gelu_exact(acc.w * rd));
    *reinterpret_cast<float4*>(g_gact + (size_t)warp * Dm + lane * 4) = o4;
}

// ---- tiled fp32 GEMM, 128x128 tile, 8x8/thread, FFMA2 + double buffer ---
// MODE 0: g_xn @ g_Wbig  -> {g_q,g_kf,g_vf,g_kg,g_vg} (+bbig)  K=128 NT=640
// MODE 1: g_gact @ out_w -> g_x1 = x + sig*(C+out_b) + (1-sig)*g_xn
// MODE 2: g_xn2 @ w1     -> g_hid = gelu(C + b1)               K=128 NT=512
// MODE 3: g_hid @ w2     -> out   = g_x1 + C + b2              K=512 NT=128
#define BM 128
#define BN 128
#define BKg 8

template <int MODE, int K, int NT>
__global__ __launch_bounds__(256, 2)
void gemm_kernel(const float* __restrict__ Bext,
                 const float* __restrict__ bias,
                 const float* __restrict__ aux,    // MODE1: x
                 const float* __restrict__ skip,   // MODE1 only
                 float* __restrict__ outp,         // MODE3: d_out
                 int M)
{
    __shared__ float As[2][BKg][BM + 4];
    __shared__ float Bs[2][BKg][BN + 4];
    const float* A;
    const float* B;
    if      (MODE == 0) { A = g_xn;   B = g_Wbig; }
    else if (MODE == 1) { A = g_gact; B = Bext; }
    else if (MODE == 2) { A = g_xn2;  B = Bext; }
    else                { A = g_hid;  B = Bext; }

    int tid = threadIdx.x;
    int m0 = blockIdx.x * BM;
    int n0 = blockIdx.y * BN;
    int tx = tid & 15, ty = tid >> 4;
    int arow = tid >> 1, akq = (tid & 1) * 4;
    int brow = tid >> 5, bcol = (tid & 31) * 4;

    // packed accumulators: acc2[i2][j] holds rows (ty*8+2*i2, ty*8+2*i2+1), col tx*8+j
    u64 acc2[4][8];
    #pragma unroll
    for (int i = 0; i < 4; i++)
        #pragma unroll
        for (int j = 0; j < 8; j++) acc2[i][j] = 0ULL;

    const int TITER = K / BKg;
    int gm_a = m0 + arow;

    // prologue: load tile 0 -> regs -> smem[0]
    float4 av = make_float4(0.f, 0.f, 0.f, 0.f);
    if (gm_a < M)
        av = *reinterpret_cast<const float4*>(A + (size_t)gm_a * K + akq);
    float4 bv = *reinterpret_cast<const float4*>(B + (size_t)brow * NT + n0 + bcol);
    As[0][akq + 0][arow] = av.x;
    As[0][akq + 1][arow] = av.y;
    As[0][akq + 2][arow] = av.z;
    As[0][akq + 3][arow] = av.w;
    *reinterpret_cast<float4*>(&Bs[0][brow][bcol]) = bv;
    __syncthreads();

    for (int t = 0; t < TITER; t++) {
        int cur = t & 1;
        if (t + 1 < TITER) {
            int k0 = (t + 1) * BKg;
            av = make_float4(0.f, 0.f, 0.f, 0.f);
            if (gm_a < M)
                av = *reinterpret_cast<const float4*>(A + (size_t)gm_a * K + k0 + akq);
            bv = *reinterpret_cast<const float4*>(B + (size_t)(k0 + brow) * NT + n0 + bcol);
        }
        #pragma unroll
        for (int k = 0; k < BKg; k++) {
            float4 a0 = *reinterpret_cast<const float4*>(&As[cur][k][ty * 8]);
            float4 a1 = *reinterpret_cast<const float4*>(&As[cur][k][ty * 8 + 4]);
            float4 b0 = *reinterpret_cast<const float4*>(&Bs[cur][k][tx * 8]);
            float4 b1 = *reinterpret_cast<const float4*>(&Bs[cur][k][tx * 8 + 4]);
            u64 ap[4];
            ap[0] = packf2(a0.x, a0.y);
            ap[1] = packf2(a0.z, a0.w);
            ap[2] = packf2(a1.x, a1.y);
            ap[3] = packf2(a1.z, a1.w);
            float brr[8] = {b0.x, b0.y, b0.z, b0.w, b1.x, b1.y, b1.z, b1.w};
            u64 bd[8];
            #pragma unroll
            for (int j = 0; j < 8; j++) bd[j] = dupf2(brr[j]);
            #pragma unroll
            for (int i = 0; i < 4; i++)
                #pragma unroll
                for (int j = 0; j < 8; j++)
                    ffma2(acc2[i][j], ap[i], bd[j]);
        }
        if (t + 1 < TITER) {
            int nxt = cur ^ 1;
            As[nxt][akq + 0][arow] = av.x;
            As[nxt][akq + 1][arow] = av.y;
            As[nxt][akq + 2][arow] = av.z;
            As[nxt][akq + 3][arow] = av.w;
            *reinterpret_cast<float4*>(&Bs[nxt][brow][bcol]) = bv;
        }
        __syncthreads();
    }

    // ----------------- epilogues -----------------
    float sig = 0.0f;
    if (MODE == 1) sig = 1.0f / (1.0f + __expf(-skip[0]));

    float* Cp = nullptr;
    if (MODE == 0) {
        switch (blockIdx.y) {
            case 0: Cp = g_q;  break;
            case 1: Cp = g_kf; break;
            case 2: Cp = g_vf; break;
            case 3: Cp = g_kg; break;
            default: Cp = g_vg; break;
        }
    }

    #pragma unroll
    for (int i2 = 0; i2 < 4; i2++) {
        #pragma unroll
        for (int half = 0; half < 2; half++) {
            int gm = m0 + ty * 8 + 2 * i2 + half;
            if (gm >= M) continue;
            #pragma unroll
            for (int j = 0; j < 8; j++) {
                float2 pr = *reinterpret_cast<float2*>(&acc2[i2][j]);
                float v = half ? pr.y : pr.x;
                int gn = n0 + tx * 8 + j;       // global output column in [0,NT)
                if (MODE == 0) {
                    v += g_bbig[gn];
                    Cp[(size_t)gm * Dm + (tx * 8 + j)] = v;
                } else if (MODE == 1) {
                    v += bias[gn];
                    float xv  = aux[(size_t)gm * Dm + gn];
                    float xnv = g_xn[(size_t)gm * Dm + gn];
                    g_x1[(size_t)gm * Dm + gn] = xv + sig * v + (1.0f - sig) * xnv;
                } else if (MODE == 2) {
                    v += bias[gn];
                    g_hid[(size_t)gm * (4 * Dm) + gn] = gelu_exact(v);
                } else {
                    v += bias[gn];
                    outp[(size_t)gm * Dm + gn] = g_x1[(size_t)gm * Dm + gn] + v;
                }
            }
        }
    }
}

// ------------------------------- launch ---------------------------------
extern "C" void kernel_launch(void* const* d_in, const int* in_sizes, int n_in,
                              void* d_out, int out_size)
{
    const float* x      = (const float*)d_in[0];
    const int*   ef     = (const int*)  d_in[1];
    const int*   eg     = (const int*)  d_in[2];
    const float* kqv_w  = (const float*)d_in[3];
    const float* kqv_b  = (const float*)d_in[4];
    const float* a_f    = (const float*)d_in[5];
    const float* m_f    = (const float*)d_in[6];
    const float* p_f    = (const float*)d_in[7];
    const float* a_g    = (const float*)d_in[8];
    const float* m_g    = (const float*)d_in[9];
    const float* p_g    = (const float*)d_in[10];
    const float* out_w  = (const float*)d_in[11];
    const float* out_b  = (const float*)d_in[12];
    const float* skip   = (const float*)d_in[13];
    const float* ln1_g  = (const float*)d_in[14];
    const float* ln1_b  = (const float*)d_in[15];
    const float* ln2_g  = (const float*)d_in[16];
    const float* ln2_b  = (const float*)d_in[17];
    const float* w1     = (const float*)d_in[18];
    const float* b1     = (const float*)d_in[19];
    const float* w2     = (const float*)d_in[20];
    const float* b2     = (const float*)d_in[21];
    float* out = (float*)d_out;

    int N = in_sizes[0] / Dm;
    int E = in_sizes[1] / 2;
    if (N > NMAX) N = NMAX;
    if (E > EMAX) E = EMAX;

    int mtiles = (N + BM - 1) / BM;

    // 1. LN1: x -> g_xn
    ln_kernel<0><<<(N + 7) / 8, 256>>>(x, ln1_g, ln1_b, N);
    // 2. fold relation matrices into Wbig/bbig
    prep_w_kernel<<<(Dm * 640 + 255) / 256, 256>>>(kqv_w, kqv_b, a_f, m_f, p_f,
                                                   a_g, m_g, p_g);
    // 3. fused projection: q,kf,vf,kg,vg
    gemm_kernel<0, 128, 640><<<dim3(mtiles, 5), 256>>>(nullptr, nullptr, nullptr,
                                                       nullptr, nullptr, N);
    // 4-7. CSR build by dst
    zero_count_kernel<<<(N + 255) / 256, 256>>>(N);
    count_kernel<<<(2 * E + 255) / 256, 256>>>(ef, eg, E);
    scan_kernel<<<1, 1024>>>(N);
    scatter_kernel<<<(2 * E + 255) / 256, 256>>>(ef, eg, E);
    // 8. fused softmax + aggregation + gelu
    agg_kernel<<<(N + 7) / 8, 256>>>(N);
    // 9. out projection + skip-mix + residual -> g_x1
    gemm_kernel<1, 128, 128><<<dim3(mtiles, 1), 256>>>(out_w, out_b, x, skip,
                                                       nullptr, N);
    // 10. LN2: g_x1 -> g_xn2
    ln_kernel<1><<<(N + 7) / 8, 256>>>(nullptr, ln2_g, ln2_b, N);
    // 11. FFN up + gelu
    gemm_kernel<2, 128, 512><<<dim3(mtiles, 4), 256>>>(w1, b1, nullptr, nullptr,
                                                       nullptr, N);
    // 12. FFN down + residual -> out
    gemm_kernel<3, 512, 128><<<dim3(mtiles, 1), 256>>>(w2, b2, nullptr, nullptr,
                                                       out, N);
}

// round 6
// speedup vs baseline: 1.4396x; 1.2450x over previous
#include <cuda_runtime.h>
#include <cuda_bf16.h>
#include <math.h>
#include <stdint.h>
#include <mma.h>

using namespace nvcuda;

// ---------------- problem-size constants (fixed dataset) ----------------
#define NMAX   50000
#define EMAX   300000
#define Dm     128
#define Hh     8
#define DHd    16

// ---------------- scratch (static device memory; no allocations) --------
__device__ float g_xn  [NMAX * Dm];
__device__ float g_q   [NMAX * Dm];
__device__ float g_kf  [NMAX * Dm];
__device__ float g_vf  [NMAX * Dm];
__device__ float g_kg  [NMAX * Dm];
__device__ float g_vg  [NMAX * Dm];
__device__ float g_gact[NMAX * Dm];
__device__ float g_x1  [NMAX * Dm];
__device__ float g_xn2 [NMAX * Dm];
__device__ float g_hid [NMAX * 4 * Dm];
__device__ float g_WbigT[640 * Dm];        // [n][k] tf32-rounded
__device__ float g_outwT[Dm * Dm];         // [n][k]
__device__ float g_w1T  [512 * Dm];        // [n][k]
__device__ float g_w2T  [Dm * 512];        // [n][k]
__device__ float g_bbig [640];
__device__ int   g_count [NMAX];
__device__ int   g_offs  [NMAX + 1];
__device__ int   g_cursor[NMAX];
__device__ int   g_entries[2 * EMAX];

__device__ __forceinline__ float gelu_exact(float v) {
    return v * 0.5f * (1.0f + erff(v * 0.70710678118654752440f));
}

__device__ __forceinline__ uint32_t tf32r(float v) {
    uint32_t r; asm("cvt.rna.tf32.f32 %0, %1;" : "=r"(r) : "f"(v)); return r;
}
__device__ __forceinline__ float tf32rf(float v) {
    uint32_t r = tf32r(v); return __uint_as_float(r);
}

// ---------------- LayerNorm: one warp per row (128 cols) ----------------
template <int WHICH>
__global__ void ln_kernel(const float* __restrict__ xin,
                          const float* __restrict__ g,
                          const float* __restrict__ b, int N)
{
    int warp = (blockIdx.x * blockDim.x + threadIdx.x) >> 5;
    int lane = threadIdx.x & 31;
    if (warp >= N) return;
    const float* in = (WHICH == 0) ? xin : g_x1;
    float*       out = (WHICH == 0) ? g_xn : g_xn2;
    float4 v = *reinterpret_cast<const float4*>(in + (size_t)warp * Dm + lane * 4);
    float s = v.x + v.y + v.z + v.w;
    #pragma unroll
    for (int o = 16; o; o >>= 1) s += __shfl_xor_sync(0xffffffffu, s, o);
    float mu = s * (1.0f / 128.0f);
    float dx = v.x - mu, dy = v.y - mu, dz = v.z - mu, dw = v.w - mu;
    float s2 = dx * dx + dy * dy + dz * dz + dw * dw;
    #pragma unroll
    for (int o = 16; o; o >>= 1) s2 += __shfl_xor_sync(0xffffffffu, s2, o);
    float r = rsqrtf(s2 * (1.0f / 128.0f) + 1e-5f);
    float4 gg = *reinterpret_cast<const float4*>(g + lane * 4);
    float4 bb = *reinterpret_cast<const float4*>(b + lane * 4);
    float4 o4 = make_float4(dx * r * gg.x + bb.x, dy * r * gg.y + bb.y,
                            dz * r * gg.z + bb.z, dw * r * gg.w + bb.w);
    *reinterpret_cast<float4*>(out + (size_t)warp * Dm + lane * 4) = o4;
}

// ---------- fold per-head relation matrices into projection weights ------
// Writes transposed [n][k], tf32-rounded.
__global__ void prep_w_kernel(const float* __restrict__ kqv_w,
                              const float* __restrict__ kqv_b,
                              const float* __restrict__ a_f,
                              const float* __restrict__ m_f,
                              const float* __restrict__ p_f,
                              const float* __restrict__ a_g,
                              const float* __restrict__ m_g,
                              const float* __restrict__ p_g)
{
    int idx = blockIdx.x * blockDim.x + threadIdx.x;
    if (idx >= Dm * 640) return;
    int n = idx % 640;
    int k = idx / 640;
    float val;
    if (n < 128) {
        val = kqv_w[k * 384 + 128 + n];         // q block
        if (k == 0) g_bbig[n] = kqv_b[128 + n];
    } else {
        int gsel = (n - 128) >> 7;              // 0:kf 1:vf 2:kg 3:vg
        int c = (n - 128) & 127;
        int h = c >> 4, f = c & 15;
        const float* mat; int srcoff; float scale = 1.0f;
        if      (gsel == 0) { mat = a_f; srcoff = 0;   scale = p_f[h] * 0.25f; }
        else if (gsel == 1) { mat = m_f; srcoff = 256; }
        else if (gsel == 2) { mat = a_g; srcoff = 0;   scale = p_g[h] * 0.25f; }
        else                { mat = m_g; srcoff = 256; }
        float s = 0.0f, bs = 0.0f;
        #pragma unroll
        for (int d = 0; d < 16; d++) {
            float w = mat[h * 256 + d * 16 + f];
            s  += kqv_w[k * 384 + srcoff + h * 16 + d] * w;
            bs += kqv_b[srcoff + h * 16 + d] * w;
        }
        val = s * scale;
        if (k == 0) g_bbig[n] = bs * scale;
    }
    g_WbigT[n * Dm + k] = tf32rf(val);
}

// ---------- transpose + tf32-round the other weights --------------------
__global__ void prep2_kernel(const float* __restrict__ out_w,
                             const float* __restrict__ w1,
                             const float* __restrict__ w2)
{
    int idx = blockIdx.x * blockDim.x + threadIdx.x;
    if (idx < 128 * 128) {
        int n = idx >> 7, k = idx & 127;
        g_outwT[n * 128 + k] = tf32rf(out_w[k * 128 + n]);
    }
    idx -= 128 * 128;
    if (idx >= 0 && idx < 512 * 128) {
        int n = idx >> 7, k = idx & 127;          // n in [0,512), k in [0,128)
        g_w1T[n * 128 + k] = tf32rf(w1[k * 512 + n]);
    }
    idx -= 512 * 128;
    if (idx >= 0 && idx < 128 * 512) {
        int n = idx >> 9, k = idx & 511;          // n in [0,128), k in [0,512)
        g_w2T[n * 512 + k] = tf32rf(w2[k * 128 + n]);
    }
}

// ---------------- CSR build: count / scan / scatter ---------------------
__global__ void zero_count_kernel(int N)
{
    int i = blockIdx.x * blockDim.x + threadIdx.x;
    if (i < N) g_count[i] = 0;
}

__global__ void count_kernel(const int* __restrict__ ef,
                             const int* __restrict__ eg, int E)
{
    int i = blockIdx.x * blockDim.x + threadIdx.x;
    if (i >= 2 * E) return;
    int dst = (i < E) ? ef[E + i] : eg[E + (i - E)];
    atomicAdd(&g_count[dst], 1);
}

__global__ void scan_kernel(int N)
{
    __shared__ int sm[1024];
    int t = threadIdx.x;
    int chunk = (N + 1023) >> 10;
    int b0 = t * chunk;
    int b1 = min(b0 + chunk, N);
    int s = 0;
    for (int i = b0; i < b1; i++) s += g_count[i];
    sm[t] = s;
    __syncthreads();
    for (int off = 1; off < 1024; off <<= 1) {
        int v = (t >= off) ? sm[t - off] : 0;
        __syncthreads();
        sm[t] += v;
        __syncthreads();
    }
    int run = sm[t] - s;    // exclusive prefix
    for (int i = b0; i < b1; i++) {
        g_offs[i] = run;
        g_cursor[i] = run;
        run += g_count[i];
    }
    if (t == 1023) g_offs[N] = sm[1023];
}

__global__ void scatter_kernel(const int* __restrict__ ef,
                               const int* __restrict__ eg, int E)
{
    int i = blockIdx.x * blockDim.x + threadIdx.x;
    if (i >= 2 * E) return;
    int src, dst, tbit;
    if (i < E) { src = ef[i];       dst = ef[E + i];       tbit = 0; }
    else       { int j = i - E; src = eg[j]; dst = eg[E + j]; tbit = 1 << 16; }
    int pos = atomicAdd(&g_cursor[dst], 1);
    g_entries[pos] = src | tbit;
}

// ------------- fused segment-softmax + aggregation + GELU ---------------
__global__ void agg_kernel(int N)
{
    int warp = (blockIdx.x * blockDim.x + threadIdx.x) >> 5;
    int lane = threadIdx.x & 31;
    if (warp >= N) return;
    float4 q4 = *reinterpret_cast<const float4*>(g_q + (size_t)warp * Dm + lane * 4);
    float4 acc = make_float4(0.f, 0.f, 0.f, 0.f);
    float denom = 0.0f;
    int beg = g_offs[warp], end = g_offs[warp + 1];
    for (int j = beg; j < end; j++) {
        int e   = g_entries[j];
        int src = e & 0xFFFF;
        const float* kp = (e & 0x10000) ? g_kg : g_kf;
        const float* vp = (e & 0x10000) ? g_vg : g_vf;
        float4 k4 = *reinterpret_cast<const float4*>(kp + (size_t)src * Dm + lane * 4);
        float p = q4.x * k4.x + q4.y * k4.y + q4.z * k4.z + q4.w * k4.w;
        p += __shfl_xor_sync(0xffffffffu, p, 1);
        p += __shfl_xor_sync(0xffffffffu, p, 2);
        float w = __expf(p);
        denom += w;
        float4 v4 = *reinterpret_cast<const float4*>(vp + (size_t)src * Dm + lane * 4);
        acc.x += w * v4.x; acc.y += w * v4.y; acc.z += w * v4.z; acc.w += w * v4.w;
    }
    float rd = 1.0f / (denom + 1e-16f);
    float4 o4 = make_float4(gelu_exact(acc.x * rd), gelu_exact(acc.y * rd),
                            gelu_exact(acc.z * rd), gelu_exact(acc.w * rd));
    *reinterpret_cast<float4*>(g_gact + (size_t)warp * Dm + lane * 4) = o4;
}

// =========== wmma tf32 GEMM: C = A[M,K] @ Bt[N,K]^T ======================
// 128x128 CTA tile; 8 warps (2Mx4N), warp tile 64x32 = 4x2 wmma m16n16k8.
// A and Bt are selected INSIDE device code (never pass __device__ symbol
// addresses from host -- host shadow reads zeros via ATS on GB300).
// MODE 0: A=g_xn,   Bt=g_WbigT -> {q,kf,vf,kg,vg}(+bbig)   K=128, 5 n-tiles
// MODE 1: A=g_gact, Bt=g_outwT -> g_x1 = x + sig*(C+b)+(1-sig)*xn  K=128
// MODE 2: A=g_xn2,  Bt=g_w1T   -> g_hid = gelu(C+b1)       K=128, 4 n-tiles
// MODE 3: A=g_hid,  Bt=g_w2T   -> out = g_x1 + C + b2      K=512 (4 chunks)
#define APAD 136
#define SM_TILE (128 * APAD)            // floats per tile buffer
#define SMEM_BYTES (2 * SM_TILE * 4)    // 139264

template <int MODE, int K>
__global__ void __launch_bounds__(256, 1)
wgemm_kernel(const float* __restrict__ bias,
             const float* __restrict__ aux,    // MODE1: x
             const float* __restrict__ skip,   // MODE1 only
             float* __restrict__ outp,         // MODE3: d_out
             int M)
{
    extern __shared__ float smem[];
    float* sA = smem;
    float* sB = smem + SM_TILE;

    int tid = threadIdx.x;
    int wid = tid >> 5;
    int m0 = blockIdx.x * 128;
    int n0 = blockIdx.y * 128;

    int warpM = wid & 1;                 // 0..1 -> 64 rows each
    int warpN = wid >> 1;                // 0..3 -> 32 cols each
    int wm = warpM * 64;
    int wn = warpN * 32;

    const float* A;
    const float* Bt;
    if      (MODE == 0) { A = g_xn;   Bt = g_WbigT; }
    else if (MODE == 1) { A = g_gact; Bt = g_outwT; }
    else if (MODE == 2) { A = g_xn2;  Bt = g_w1T;   }
    else                { A = g_hid;  Bt = g_w2T;   }

    wmma::fragment<wmma::accumulator, 16, 16, 8, float> acc[4][2];
    #pragma unroll
    for (int i = 0; i < 4; i++)
        #pragma unroll
        for (int j = 0; j < 2; j++)
            wmma::fill_fragment(acc[i][j], 0.0f);

    for (int kc = 0; kc < K; kc += 128) {
        // ---- stage A (tf32-rounded) and B tiles, row stride APAD ----
        #pragma unroll 2
        for (int i = tid; i < 128 * 32; i += 256) {
            int row = i >> 5, q = i & 31;
            int gm = m0 + row;
            float4 v = make_float4(0.f, 0.f, 0.f, 0.f);
            if (gm < M)
                v = *reinterpret_cast<const float4*>(A + (size_t)gm * K + kc + q * 4);
            v.x = tf32rf(v.x); v.y = tf32rf(v.y); v.z = tf32rf(v.z); v.w = tf32rf(v.w);
            *reinterpret_cast<float4*>(&sA[row * APAD + q * 4]) = v;
            float4 bv = *reinterpret_cast<const float4*>(
                Bt + (size_t)(n0 + row) * K + kc + q * 4);
            *reinterpret_cast<float4*>(&sB[row * APAD + q * 4]) = bv;
        }
        __syncthreads();

        // ---- 16 k-steps of wmma m16n16k8 ----
        #pragma unroll
        for (int ks = 0; ks < 16; ks++) {
            wmma::fragment<wmma::matrix_a, 16, 16, 8, wmma::precision::tf32,
                           wmma::row_major> af[4];
            wmma::fragment<wmma::matrix_b, 16, 16, 8, wmma::precision::tf32,
                           wmma::col_major> bf[2];
            #pragma unroll
            for (int i = 0; i < 4; i++)
                wmma::load_matrix_sync(af[i], &sA[(wm + i * 16) * APAD + ks * 8], APAD);
            #pragma unroll
            for (int j = 0; j < 2; j++)
                wmma::load_matrix_sync(bf[j], &sB[(wn + j * 16) * APAD + ks * 8], APAD);
            #pragma unroll
            for (int i = 0; i < 4; i++)
                #pragma unroll
                for (int j = 0; j < 2; j++)
                    wmma::mma_sync(acc[i][j], af[i], bf[j], acc[i][j]);
        }
        __syncthreads();
    }

    // ---- dump C tile into sA, then fused coalesced epilogue ----
    #pragma unroll
    for (int i = 0; i < 4; i++)
        #pragma unroll
        for (int j = 0; j < 2; j++)
            wmma::store_matrix_sync(&sA[(wm + i * 16) * APAD + wn + j * 16],
                                    acc[i][j], APAD, wmma::mem_row_major);
    __syncthreads();

    float sig = 0.0f;
    if (MODE == 1) sig = 1.0f / (1.0f + __expf(-skip[0]));
    float* Cp = nullptr;
    if (MODE == 0) {
        switch (blockIdx.y) {
            case 0: Cp = g_q;  break;
            case 1: Cp = g_kf; break;
            case 2: Cp = g_vf; break;
            case 3: Cp = g_kg; break;
            default: Cp = g_vg; break;
        }
    }

    #pragma unroll 2
    for (int i = tid; i < 128 * 32; i += 256) {
        int row = i >> 5, q = i & 31;
        int gm = m0 + row;
        if (gm >= M) continue;
        float4 v = *reinterpret_cast<float4*>(&sA[row * APAD + q * 4]);
        int gn = n0 + q * 4;
        if (MODE == 0) {
            float4 bb = *reinterpret_cast<const float4*>(g_bbig + gn);
            v.x += bb.x; v.y += bb.y; v.z += bb.z; v.w += bb.w;
            *reinterpret_cast<float4*>(Cp + (size_t)gm * Dm + q * 4) = v;
        } else if (MODE == 1) {
            float4 bb = *reinterpret_cast<const float4*>(bias + gn);
            float4 xv = *reinterpret_cast<const float4*>(aux + (size_t)gm * Dm + gn);
            float4 xn = *reinterpret_cast<const float4*>(g_xn + (size_t)gm * Dm + gn);
            float om = 1.0f - sig;
            v.x = xv.x + sig * (v.x + bb.x) + om * xn.x;
            v.y = xv.y + sig * (v.y + bb.y) + om * xn.y;
            v.z = xv.z + sig * (v.z + bb.z) + om * xn.z;
            v.w = xv.w + sig * (v.w + bb.w) + om * xn.w;
            *reinterpret_cast<float4*>(g_x1 + (size_t)gm * Dm + gn) = v;
        } else if (MODE == 2) {
            float4 bb = *reinterpret_cast<const float4*>(bias + gn);
            v.x = gelu_exact(v.x + bb.x);
            v.y = gelu_exact(v.y + bb.y);
            v.z = gelu_exact(v.z + bb.z);
            v.w = gelu_exact(v.w + bb.w);
            *reinterpret_cast<float4*>(g_hid + (size_t)gm * 512 + gn) = v;
        } else {
            float4 bb = *reinterpret_cast<const float4*>(bias + gn);
            float4 x1 = *reinterpret_cast<const float4*>(g_x1 + (size_t)gm * Dm + gn);
            v.x = x1.x + v.x + bb.x;
            v.y = x1.y + v.y + bb.y;
            v.z = x1.z + v.z + bb.z;
            v.w = x1.w + v.w + bb.w;
            *reinterpret_cast<float4*>(outp + (size_t)gm * Dm + gn) = v;
        }
    }
}

// ------------------------------- launch ---------------------------------
extern "C" void kernel_launch(void* const* d_in, const int* in_sizes, int n_in,
                              void* d_out, int out_size)
{
    const float* x      = (const float*)d_in[0];
    const int*   ef     = (const int*)  d_in[1];
    const int*   eg     = (const int*)  d_in[2];
    const float* kqv_w  = (const float*)d_in[3];
    const float* kqv_b  = (const float*)d_in[4];
    const float* a_f    = (const float*)d_in[5];
    const float* m_f    = (const float*)d_in[6];
    const float* p_f    = (const float*)d_in[7];
    const float* a_g    = (const float*)d_in[8];
    const float* m_g    = (const float*)d_in[9];
    const float* p_g    = (const float*)d_in[10];
    const float* out_w  = (const float*)d_in[11];
    const float* out_b  = (const float*)d_in[12];
    const float* skip   = (const float*)d_in[13];
    const float* ln1_g  = (const float*)d_in[14];
    const float* ln1_b  = (const float*)d_in[15];
    const float* ln2_g  = (const float*)d_in[16];
    const float* ln2_b  = (const float*)d_in[17];
    const float* w1     = (const float*)d_in[18];
    const float* b1     = (const float*)d_in[19];
    const float* w2     = (const float*)d_in[20];
    const float* b2     = (const float*)d_in[21];
    float* out = (float*)d_out;

    int N = in_sizes[0] / Dm;
    int E = in_sizes[1] / 2;
    if (N > NMAX) N = NMAX;
    if (E > EMAX) E = EMAX;

    int mtiles = (N + 127) / 128;

    cudaFuncSetAttribute(wgemm_kernel<0, 128>, cudaFuncAttributeMaxDynamicSharedMemorySize, SMEM_BYTES);
    cudaFuncSetAttribute(wgemm_kernel<1, 128>, cudaFuncAttributeMaxDynamicSharedMemorySize, SMEM_BYTES);
    cudaFuncSetAttribute(wgemm_kernel<2, 128>, cudaFuncAttributeMaxDynamicSharedMemorySize, SMEM_BYTES);
    cudaFuncSetAttribute(wgemm_kernel<3, 512>, cudaFuncAttributeMaxDynamicSharedMemorySize, SMEM_BYTES);

    // 0. LN1: x -> g_xn
    ln_kernel<0><<<(N + 7) / 8, 256>>>(x, ln1_g, ln1_b, N);
    // 1. fold relation matrices into WbigT/bbig (transposed, tf32)
    prep_w_kernel<<<(Dm * 640 + 255) / 256, 256>>>(kqv_w, kqv_b, a_f, m_f, p_f,
                                                   a_g, m_g, p_g);
    // 2. transpose + round remaining weights
    prep2_kernel<<<(147456 + 255) / 256, 256>>>(out_w, w1, w2);
    // 3. fused projection GEMM (wmma tf32): q,kf,vf,kg,vg
    wgemm_kernel<0, 128><<<dim3(mtiles, 5), 256, SMEM_BYTES>>>(
        nullptr, nullptr, nullptr, nullptr, N);
    // 4-7. CSR build by dst
    zero_count_kernel<<<(N + 255) / 256, 256>>>(N);
    count_kernel<<<(2 * E + 255) / 256, 256>>>(ef, eg, E);
    scan_kernel<<<1, 1024>>>(N);
    scatter_kernel<<<(2 * E + 255) / 256, 256>>>(ef, eg, E);
    // 8. fused softmax + aggregation + gelu
    agg_kernel<<<(N + 7) / 8, 256>>>(N);
    // 9. out projection + skip-mix + residual -> g_x1
    wgemm_kernel<1, 128><<<dim3(mtiles, 1), 256, SMEM_BYTES>>>(
        out_b, x, skip, nullptr, N);
    // 10. LN2: g_x1 -> g_xn2
    ln_kernel<1><<<(N + 7) / 8, 256>>>(nullptr, ln2_g, ln2_b, N);
    // 11. FFN up + gelu
    wgemm_kernel<2, 128><<<dim3(mtiles, 4), 256, SMEM_BYTES>>>(
        b1, nullptr, nullptr, nullptr, N);
    // 12. FFN down + residual -> out
    wgemm_kernel<3, 512><<<dim3(mtiles, 1), 256, SMEM_BYTES>>>(
        b2, nullptr, nullptr, out, N);
}

// round 7
// speedup vs baseline: 1.5634x; 1.0860x over previous
#include <cuda_runtime.h>
#include <cuda_bf16.h>
#include <math.h>
#include <stdint.h>
#include <mma.h>

using namespace nvcuda;

// ---------------- problem-size constants (fixed dataset) ----------------
#define NMAX   50000
#define EMAX   300000
#define Dm     128
#define Hh     8
#define DHd    16

// ---------------- scratch (static device memory; no allocations) --------
__device__ float g_xn  [NMAX * Dm];
__device__ float g_q   [NMAX * Dm];
__device__ float g_kf  [NMAX * Dm];
__device__ float g_vf  [NMAX * Dm];
__device__ float g_kg  [NMAX * Dm];
__device__ float g_vg  [NMAX * Dm];
__device__ float g_gact[NMAX * Dm];
__device__ float g_x1  [NMAX * Dm];
__device__ float g_xn2 [NMAX * Dm];
__device__ float g_hid [NMAX * 4 * Dm];
__device__ float g_WbigT[640 * Dm];        // [n][k] tf32-rounded
__device__ float g_outwT[Dm * Dm];         // [n][k]
__device__ float g_w1T  [512 * Dm];        // [n][k]
__device__ float g_w2T  [Dm * 512];        // [n][k]
__device__ float g_bbig [640];
__device__ int   g_count [NMAX];
__device__ int   g_offs  [NMAX + 1];
__device__ int   g_cursor[NMAX];
__device__ int   g_entries[2 * EMAX];

__device__ __forceinline__ float gelu_exact(float v) {
    return v * 0.5f * (1.0f + erff(v * 0.70710678118654752440f));
}

__device__ __forceinline__ uint32_t tf32r(float v) {
    uint32_t r; asm("cvt.rna.tf32.f32 %0, %1;" : "=r"(r) : "f"(v)); return r;
}
__device__ __forceinline__ float tf32rf(float v) {
    uint32_t r = tf32r(v); return __uint_as_float(r);
}

// ---------------- LayerNorm: one warp per row (128 cols) ----------------
template <int WHICH>
__global__ void ln_kernel(const float* __restrict__ xin,
                          const float* __restrict__ g,
                          const float* __restrict__ b, int N)
{
    int warp = (blockIdx.x * blockDim.x + threadIdx.x) >> 5;
    int lane = threadIdx.x & 31;
    if (warp >= N) return;
    const float* in = (WHICH == 0) ? xin : g_x1;
    float*       out = (WHICH == 0) ? g_xn : g_xn2;
    float4 v = *reinterpret_cast<const float4*>(in + (size_t)warp * Dm + lane * 4);
    float s = v.x + v.y + v.z + v.w;
    #pragma unroll
    for (int o = 16; o; o >>= 1) s += __shfl_xor_sync(0xffffffffu, s, o);
    float mu = s * (1.0f / 128.0f);
    float dx = v.x - mu, dy = v.y - mu, dz = v.z - mu, dw = v.w - mu;
    float s2 = dx * dx + dy * dy + dz * dz + dw * dw;
    #pragma unroll
    for (int o = 16; o; o >>= 1) s2 += __shfl_xor_sync(0xffffffffu, s2, o);
    float r = rsqrtf(s2 * (1.0f / 128.0f) + 1e-5f);
    float4 gg = *reinterpret_cast<const float4*>(g + lane * 4);
    float4 bb = *reinterpret_cast<const float4*>(b + lane * 4);
    float4 o4 = make_float4(dx * r * gg.x + bb.x, dy * r * gg.y + bb.y,
                            dz * r * gg.z + bb.z, dw * r * gg.w + bb.w);
    *reinterpret_cast<float4*>(out + (size_t)warp * Dm + lane * 4) = o4;
}

// ---------- fold per-head relation matrices into projection weights ------
// Writes transposed [n][k], tf32-rounded.
__global__ void prep_w_kernel(const float* __restrict__ kqv_w,
                              const float* __restrict__ kqv_b,
                              const float* __restrict__ a_f,
                              const float* __restrict__ m_f,
                              const float* __restrict__ p_f,
                              const float* __restrict__ a_g,
                              const float* __restrict__ m_g,
                              const float* __restrict__ p_g)
{
    int idx = blockIdx.x * blockDim.x + threadIdx.x;
    if (idx >= Dm * 640) return;
    int n = idx % 640;
    int k = idx / 640;
    float val;
    if (n < 128) {
        val = kqv_w[k * 384 + 128 + n];         // q block
        if (k == 0) g_bbig[n] = kqv_b[128 + n];
    } else {
        int gsel = (n - 128) >> 7;              // 0:kf 1:vf 2:kg 3:vg
        int c = (n - 128) & 127;
        int h = c >> 4, f = c & 15;
        const float* mat; int srcoff; float scale = 1.0f;
        if      (gsel == 0) { mat = a_f; srcoff = 0;   scale = p_f[h] * 0.25f; }
        else if (gsel == 1) { mat = m_f; srcoff = 256; }
        else if (gsel == 2) { mat = a_g; srcoff = 0;   scale = p_g[h] * 0.25f; }
        else                { mat = m_g; srcoff = 256; }
        float s = 0.0f, bs = 0.0f;
        #pragma unroll
        for (int d = 0; d < 16; d++) {
            float w = mat[h * 256 + d * 16 + f];
            s  += kqv_w[k * 384 + srcoff + h * 16 + d] * w;
            bs += kqv_b[srcoff + h * 16 + d] * w;
        }
        val = s * scale;
        if (k == 0) g_bbig[n] = bs * scale;
    }
    g_WbigT[n * Dm + k] = tf32rf(val);
}

// ---------- transpose + tf32-round the other weights --------------------
__global__ void prep2_kernel(const float* __restrict__ out_w,
                             const float* __restrict__ w1,
                             const float* __restrict__ w2)
{
    int idx = blockIdx.x * blockDim.x + threadIdx.x;
    if (idx < 128 * 128) {
        int n = idx >> 7, k = idx & 127;
        g_outwT[n * 128 + k] = tf32rf(out_w[k * 128 + n]);
    }
    idx -= 128 * 128;
    if (idx >= 0 && idx < 512 * 128) {
        int n = idx >> 7, k = idx & 127;          // n in [0,512), k in [0,128)
        g_w1T[n * 128 + k] = tf32rf(w1[k * 512 + n]);
    }
    idx -= 512 * 128;
    if (idx >= 0 && idx < 128 * 512) {
        int n = idx >> 9, k = idx & 511;          // n in [0,128), k in [0,512)
        g_w2T[n * 512 + k] = tf32rf(w2[k * 128 + n]);
    }
}

// ---------------- CSR build: count / scan / scatter ---------------------
__global__ void zero_count_kernel(int N)
{
    int i = blockIdx.x * blockDim.x + threadIdx.x;
    if (i < N) g_count[i] = 0;
}

__global__ void count_kernel(const int* __restrict__ ef,
                             const int* __restrict__ eg, int E)
{
    int i = blockIdx.x * blockDim.x + threadIdx.x;
    if (i >= 2 * E) return;
    int dst = (i < E) ? ef[E + i] : eg[E + (i - E)];
    atomicAdd(&g_count[dst], 1);
}

__global__ void scan_kernel(int N)
{
    __shared__ int sm[1024];
    int t = threadIdx.x;
    int chunk = (N + 1023) >> 10;
    int b0 = t * chunk;
    int b1 = min(b0 + chunk, N);
    int s = 0;
    for (int i = b0; i < b1; i++) s += g_count[i];
    sm[t] = s;
    __syncthreads();
    for (int off = 1; off < 1024; off <<= 1) {
        int v = (t >= off) ? sm[t - off] : 0;
        __syncthreads();
        sm[t] += v;
        __syncthreads();
    }
    int run = sm[t] - s;    // exclusive prefix
    for (int i = b0; i < b1; i++) {
        g_offs[i] = run;
        g_cursor[i] = run;
        run += g_count[i];
    }
    if (t == 1023) g_offs[N] = sm[1023];
}

__global__ void scatter_kernel(const int* __restrict__ ef,
                               const int* __restrict__ eg, int E)
{
    int i = blockIdx.x * blockDim.x + threadIdx.x;
    if (i >= 2 * E) return;
    int src, dst, tbit;
    if (i < E) { src = ef[i];       dst = ef[E + i];       tbit = 0; }
    else       { int j = i - E; src = eg[j]; dst = eg[E + j]; tbit = 1 << 16; }
    int pos = atomicAdd(&g_cursor[dst], 1);
    g_entries[pos] = src | tbit;
}

// ------------- fused segment-softmax + aggregation + GELU ---------------
// 2-wide unrolled: issue both edges' k/v loads before consuming (MLP 4).
__global__ void agg_kernel(int N)
{
    int warp = (blockIdx.x * blockDim.x + threadIdx.x) >> 5;
    int lane = threadIdx.x & 31;
    if (warp >= N) return;
    float4 q4 = *reinterpret_cast<const float4*>(g_q + (size_t)warp * Dm + lane * 4);
    float4 acc = make_float4(0.f, 0.f, 0.f, 0.f);
    float denom = 0.0f;
    int beg = g_offs[warp], end = g_offs[warp + 1];
    int j = beg;
    for (; j + 2 <= end; j += 2) {
        int e0 = g_entries[j];
        int e1 = g_entries[j + 1];
        int s0 = e0 & 0xFFFF, s1 = e1 & 0xFFFF;
        const float* kp0 = (e0 & 0x10000) ? g_kg : g_kf;
        const float* vp0 = (e0 & 0x10000) ? g_vg : g_vf;
        const float* kp1 = (e1 & 0x10000) ? g_kg : g_kf;
        const float* vp1 = (e1 & 0x10000) ? g_vg : g_vf;
        float4 k0 = *reinterpret_cast<const float4*>(kp0 + (size_t)s0 * Dm + lane * 4);
        float4 v0 = *reinterpret_cast<const float4*>(vp0 + (size_t)s0 * Dm + lane * 4);
        float4 k1 = *reinterpret_cast<const float4*>(kp1 + (size_t)s1 * Dm + lane * 4);
        float4 v1 = *reinterpret_cast<const float4*>(vp1 + (size_t)s1 * Dm + lane * 4);
        float p0 = q4.x * k0.x + q4.y * k0.y + q4.z * k0.z + q4.w * k0.w;
        float p1 = q4.x * k1.x + q4.y * k1.y + q4.z * k1.z + q4.w * k1.w;
        p0 += __shfl_xor_sync(0xffffffffu, p0, 1);
        p1 += __shfl_xor_sync(0xffffffffu, p1, 1);
        p0 += __shfl_xor_sync(0xffffffffu, p0, 2);
        p1 += __shfl_xor_sync(0xffffffffu, p1, 2);
        float w0 = __expf(p0);
        float w1 = __expf(p1);
        denom += w0 + w1;
        acc.x += w0 * v0.x + w1 * v1.x;
        acc.y += w0 * v0.y + w1 * v1.y;
        acc.z += w0 * v0.z + w1 * v1.z;
        acc.w += w0 * v0.w + w1 * v1.w;
    }
    for (; j < end; j++) {
        int e   = g_entries[j];
        int src = e & 0xFFFF;
        const float* kp = (e & 0x10000) ? g_kg : g_kf;
        const float* vp = (e & 0x10000) ? g_vg : g_vf;
        float4 k4 = *reinterpret_cast<const float4*>(kp + (size_t)src * Dm + lane * 4);
        float4 v4 = *reinterpret_cast<const float4*>(vp + (size_t)src * Dm + lane * 4);
        float p = q4.x * k4.x + q4.y * k4.y + q4.z * k4.z + q4.w * k4.w;
        p += __shfl_xor_sync(0xffffffffu, p, 1);
        p += __shfl_xor_sync(0xffffffffu, p, 2);
        float w = __expf(p);
        denom += w;
        acc.x += w * v4.x; acc.y += w * v4.y; acc.z += w * v4.z; acc.w += w * v4.w;
    }
    float rd = 1.0f / (denom + 1e-16f);
    float4 o4 = make_float4(gelu_exact(acc.x * rd), gelu_exact(acc.y * rd),
                            gelu_exact(acc.z * rd), gelu_exact(acc.w * rd));
    *reinterpret_cast<float4*>(g_gact + (size_t)warp * Dm + lane * 4) = o4;
}

// =========== wmma tf32 GEMM: C = A[M,K] @ Bt[N,K]^T ======================
// 128x128 CTA tile; 512 threads = 16 warps (4Mx4N), warp tile 32x32 =
// 2x2 wmma m16n16k8 frags. A/Bt selected inside device code.
// MODE 0: A=g_xn,   Bt=g_WbigT -> {q,kf,vf,kg,vg}(+bbig)   K=128, 5 n-tiles
// MODE 1: A=g_gact, Bt=g_outwT -> g_x1 = x + sig*(C+b)+(1-sig)*xn  K=128
// MODE 2: A=g_xn2,  Bt=g_w1T   -> g_hid = gelu(C+b1)       K=128, 4 n-tiles
// MODE 3: A=g_hid,  Bt=g_w2T   -> out = g_x1 + C + b2      K=512 (4 chunks)
#define APAD 136
#define SM_TILE (128 * APAD)            // floats per tile buffer
#define SMEM_BYTES (2 * SM_TILE * 4)    // 139264

template <int MODE, int K>
__global__ void __launch_bounds__(512, 1)
wgemm_kernel(const float* __restrict__ bias,
             const float* __restrict__ aux,    // MODE1: x
             const float* __restrict__ skip,   // MODE1 only
             float* __restrict__ outp,         // MODE3: d_out
             int M)
{
    extern __shared__ float smem[];
    float* sA = smem;
    float* sB = smem + SM_TILE;

    int tid = threadIdx.x;
    int wid = tid >> 5;
    int m0 = blockIdx.x * 128;
    int n0 = blockIdx.y * 128;

    int wm = (wid & 3) * 32;             // 4 M groups of 32 rows
    int wn = (wid >> 2) * 32;            // 4 N groups of 32 cols

    const float* A;
    const float* Bt;
    if      (MODE == 0) { A = g_xn;   Bt = g_WbigT; }
    else if (MODE == 1) { A = g_gact; Bt = g_outwT; }
    else if (MODE == 2) { A = g_xn2;  Bt = g_w1T;   }
    else                { A = g_hid;  Bt = g_w2T;   }

    wmma::fragment<wmma::accumulator, 16, 16, 8, float> acc[2][2];
    #pragma unroll
    for (int i = 0; i < 2; i++)
        #pragma unroll
        for (int j = 0; j < 2; j++)
            wmma::fill_fragment(acc[i][j], 0.0f);

    for (int kc = 0; kc < K; kc += 128) {
        // ---- stage A (tf32-rounded) and B tiles, row stride APAD ----
        #pragma unroll 2
        for (int i = tid; i < 128 * 32; i += 512) {
            int row = i >> 5, q = i & 31;
            int gm = m0 + row;
            float4 v = make_float4(0.f, 0.f, 0.f, 0.f);
            if (gm < M)
                v = *reinterpret_cast<const float4*>(A + (size_t)gm * K + kc + q * 4);
            v.x = tf32rf(v.x); v.y = tf32rf(v.y); v.z = tf32rf(v.z); v.w = tf32rf(v.w);
            *reinterpret_cast<float4*>(&sA[row * APAD + q * 4]) = v;
            float4 bv = *reinterpret_cast<const float4*>(
                Bt + (size_t)(n0 + row) * K + kc + q * 4);
            *reinterpret_cast<float4*>(&sB[row * APAD + q * 4]) = bv;
        }
        __syncthreads();

        // ---- 16 k-steps of wmma m16n16k8 ----
        #pragma unroll
        for (int ks = 0; ks < 16; ks++) {
            wmma::fragment<wmma::matrix_a, 16, 16, 8, wmma::precision::tf32,
                           wmma::row_major> af[2];
            wmma::fragment<wmma::matrix_b, 16, 16, 8, wmma::precision::tf32,
                           wmma::col_major> bf[2];
            #pragma unroll
            for (int i = 0; i < 2; i++)
                wmma::load_matrix_sync(af[i], &sA[(wm + i * 16) * APAD + ks * 8], APAD);
            #pragma unroll
            for (int j = 0; j < 2; j++)
                wmma::load_matrix_sync(bf[j], &sB[(wn + j * 16) * APAD + ks * 8], APAD);
            #pragma unroll
            for (int i = 0; i < 2; i++)
                #pragma unroll
                for (int j = 0; j < 2; j++)
                    wmma::mma_sync(acc[i][j], af[i], bf[j], acc[i][j]);
        }
        __syncthreads();
    }

    // ---- dump C tile into sA, then fused coalesced epilogue ----
    #pragma unroll
    for (int i = 0; i < 2; i++)
        #pragma unroll
        for (int j = 0; j < 2; j++)
            wmma::store_matrix_sync(&sA[(wm + i * 16) * APAD + wn + j * 16],
                                    acc[i][j], APAD, wmma::mem_row_major);
    __syncthreads();

    float sig = 0.0f;
    if (MODE == 1) sig = 1.0f / (1.0f + __expf(-skip[0]));
    float* Cp = nullptr;
    if (MODE == 0) {
        switch (blockIdx.y) {
            case 0: Cp = g_q;  break;
            case 1: Cp = g_kf; break;
            case 2: Cp = g_vf; break;
            case 3: Cp = g_kg; break;
            default: Cp = g_vg; break;
        }
    }

    #pragma unroll 2
    for (int i = tid; i < 128 * 32; i += 512) {
        int row = i >> 5, q = i & 31;
        int gm = m0 + row;
        if (gm >= M) continue;
        float4 v = *reinterpret_cast<float4*>(&sA[row * APAD + q * 4]);
        int gn = n0 + q * 4;
        if (MODE == 0) {
            float4 bb = *reinterpret_cast<const float4*>(g_bbig + gn);
            v.x += bb.x; v.y += bb.y; v.z += bb.z; v.w += bb.w;
            *reinterpret_cast<float4*>(Cp + (size_t)gm * Dm + q * 4) = v;
        } else if (MODE == 1) {
            float4 bb = *reinterpret_cast<const float4*>(bias + gn);
            float4 xv = *reinterpret_cast<const float4*>(aux + (size_t)gm * Dm + gn);
            float4 xn = *reinterpret_cast<const float4*>(g_xn + (size_t)gm * Dm + gn);
            float om = 1.0f - sig;
            v.x = xv.x + sig * (v.x + bb.x) + om * xn.x;
            v.y = xv.y + sig * (v.y + bb.y) + om * xn.y;
            v.z = xv.z + sig * (v.z + bb.z) + om * xn.z;
            v.w = xv.w + sig * (v.w + bb.w) + om * xn.w;
            *reinterpret_cast<float4*>(g_x1 + (size_t)gm * Dm + gn) = v;
        } else if (MODE == 2) {
            float4 bb = *reinterpret_cast<const float4*>(bias + gn);
            v.x = gelu_exact(v.x + bb.x);
            v.y = gelu_exact(v.y + bb.y);
            v.z = gelu_exact(v.z + bb.z);
            v.w = gelu_exact(v.w + bb.w);
            *reinterpret_cast<float4*>(g_hid + (size_t)gm * 512 + gn) = v;
        } else {
            float4 bb = *reinterpret_cast<const float4*>(bias + gn);
            float4 x1 = *reinterpret_cast<const float4*>(g_x1 + (size_t)gm * Dm + gn);
            v.x = x1.x + v.x + bb.x;
            v.y = x1.y + v.y + bb.y;
            v.z = x1.z + v.z + bb.z;
            v.w = x1.w + v.w + bb.w;
            *reinterpret_cast<float4*>(outp + (size_t)gm * Dm + gn) = v;
        }
    }
}

// ------------------------------- launch ---------------------------------
extern "C" void kernel_launch(void* const* d_in, const int* in_sizes, int n_in,
                              void* d_out, int out_size)
{
    const float* x      = (const float*)d_in[0];
    const int*   ef     = (const int*)  d_in[1];
    const int*   eg     = (const int*)  d_in[2];
    const float* kqv_w  = (const float*)d_in[3];
    const float* kqv_b  = (const float*)d_in[4];
    const float* a_f    = (const float*)d_in[5];
    const float* m_f    = (const float*)d_in[6];
    const float* p_f    = (const float*)d_in[7];
    const float* a_g    = (const float*)d_in[8];
    const float* m_g    = (const float*)d_in[9];
    const float* p_g    = (const float*)d_in[10];
    const float* out_w  = (const float*)d_in[11];
    const float* out_b  = (const float*)d_in[12];
    const float* skip   = (const float*)d_in[13];
    const float* ln1_g  = (const float*)d_in[14];
    const float* ln1_b  = (const float*)d_in[15];
    const float* ln2_g  = (const float*)d_in[16];
    const float* ln2_b  = (const float*)d_in[17];
    const float* w1     = (const float*)d_in[18];
    const float* b1     = (const float*)d_in[19];
    const float* w2     = (const float*)d_in[20];
    const float* b2     = (const float*)d_in[21];
    float* out = (float*)d_out;

    int N = in_sizes[0] / Dm;
    int E = in_sizes[1] / 2;
    if (N > NMAX) N = NMAX;
    if (E > EMAX) E = EMAX;

    int mtiles = (N + 127) / 128;

    cudaFuncSetAttribute(wgemm_kernel<0, 128>, cudaFuncAttributeMaxDynamicSharedMemorySize, SMEM_BYTES);
    cudaFuncSetAttribute(wgemm_kernel<1, 128>, cudaFuncAttributeMaxDynamicSharedMemorySize, SMEM_BYTES);
    cudaFuncSetAttribute(wgemm_kernel<2, 128>, cudaFuncAttributeMaxDynamicSharedMemorySize, SMEM_BYTES);
    cudaFuncSetAttribute(wgemm_kernel<3, 512>, cudaFuncAttributeMaxDynamicSharedMemorySize, SMEM_BYTES);

    // 0. LN1: x -> g_xn
    ln_kernel<0><<<(N + 7) / 8, 256>>>(x, ln1_g, ln1_b, N);
    // 1. fold relation matrices into WbigT/bbig (transposed, tf32)
    prep_w_kernel<<<(Dm * 640 + 255) / 256, 256>>>(kqv_w, kqv_b, a_f, m_f, p_f,
                                                   a_g, m_g, p_g);
    // 2. transpose + round remaining weights
    prep2_kernel<<<(147456 + 255) / 256, 256>>>(out_w, w1, w2);
    // 3. fused projection GEMM (wmma tf32): q,kf,vf,kg,vg
    wgemm_kernel<0, 128><<<dim3(mtiles, 5), 512, SMEM_BYTES>>>(
        nullptr, nullptr, nullptr, nullptr, N);
    // 4-7. CSR build by dst
    zero_count_kernel<<<(N + 255) / 256, 256>>>(N);
    count_kernel<<<(2 * E + 255) / 256, 256>>>(ef, eg, E);
    scan_kernel<<<1, 1024>>>(N);
    scatter_kernel<<<(2 * E + 255) / 256, 256>>>(ef, eg, E);
    // 8. fused softmax + aggregation + gelu
    agg_kernel<<<(N + 7) / 8, 256>>>(N);
    // 9. out projection + skip-mix + residual -> g_x1
    wgemm_kernel<1, 128><<<dim3(mtiles, 1), 512, SMEM_BYTES>>>(
        out_b, x, skip, nullptr, N);
    // 10. LN2: g_x1 -> g_xn2
    ln_kernel<1><<<(N + 7) / 8, 256>>>(nullptr, ln2_g, ln2_b, N);
    // 11. FFN up + gelu
    wgemm_kernel<2, 128><<<dim3(mtiles, 4), 512, SMEM_BYTES>>>(
        b1, nullptr, nullptr, nullptr, N);
    // 12. FFN down + residual -> out
    wgemm_kernel<3, 512><<<dim3(mtiles, 1), 512, SMEM_BYTES>>>(
        b2, nullptr, nullptr, out, N);
}

// round 8
// speedup vs baseline: 2.6428x; 1.6904x over previous
#include <cuda_runtime.h>
#include <cuda_fp16.h>
#include <math.h>
#include <stdint.h>
#include <mma.h>

using namespace nvcuda;

// ---------------- problem-size constants (fixed dataset) ----------------
#define NMAX   50000
#define EMAX   300000
#define Dm     128
#define Hh     8
#define DHd    16

// ---------------- scratch (static device memory; no allocations) --------
__device__ float g_xn  [NMAX * Dm];
__device__ float g_q   [NMAX * Dm];
__device__ float g_kf  [NMAX * Dm];
__device__ float g_vf  [NMAX * Dm];
__device__ float g_kg  [NMAX * Dm];
__device__ float g_vg  [NMAX * Dm];
__device__ float g_gact[NMAX * Dm];
__device__ float g_x1  [NMAX * Dm];
__device__ float g_xn2 [NMAX * Dm];
__device__ float g_hid [NMAX * 4 * Dm];
__device__ __half g_WbigTh[640 * Dm];      // [n][k] fp16
__device__ __half g_outwTh[Dm * Dm];       // [n][k]
__device__ __half g_w1Th  [512 * Dm];      // [n][k]
__device__ __half g_w2Th  [Dm * 512];      // [n][k]
__device__ float g_bbig [640];
__device__ int   g_count [NMAX];
__device__ int   g_offs  [NMAX + 1];
__device__ int   g_cursor[NMAX];
__device__ int   g_entries[2 * EMAX];

__device__ __forceinline__ float gelu_exact(float v) {
    return v * 0.5f * (1.0f + erff(v * 0.70710678118654752440f));
}

// ---------------- LayerNorm: one warp per row (128 cols) ----------------
template <int WHICH>
__global__ void ln_kernel(const float* __restrict__ xin,
                          const float* __restrict__ g,
                          const float* __restrict__ b, int N)
{
    int warp = (blockIdx.x * blockDim.x + threadIdx.x) >> 5;
    int lane = threadIdx.x & 31;
    if (warp >= N) return;
    const float* in = (WHICH == 0) ? xin : g_x1;
    float*       out = (WHICH == 0) ? g_xn : g_xn2;
    float4 v = *reinterpret_cast<const float4*>(in + (size_t)warp * Dm + lane * 4);
    float s = v.x + v.y + v.z + v.w;
    #pragma unroll
    for (int o = 16; o; o >>= 1) s += __shfl_xor_sync(0xffffffffu, s, o);
    float mu = s * (1.0f / 128.0f);
    float dx = v.x - mu, dy = v.y - mu, dz = v.z - mu, dw = v.w - mu;
    float s2 = dx * dx + dy * dy + dz * dz + dw * dw;
    #pragma unroll
    for (int o = 16; o; o >>= 1) s2 += __shfl_xor_sync(0xffffffffu, s2, o);
    float r = rsqrtf(s2 * (1.0f / 128.0f) + 1e-5f);
    float4 gg = *reinterpret_cast<const float4*>(g + lane * 4);
    float4 bb = *reinterpret_cast<const float4*>(b + lane * 4);
    float4 o4 = make_float4(dx * r * gg.x + bb.x, dy * r * gg.y + bb.y,
                            dz * r * gg.z + bb.z, dw * r * gg.w + bb.w);
    *reinterpret_cast<float4*>(out + (size_t)warp * Dm + lane * 4) = o4;
}

// ---------- fold per-head relation matrices into projection weights ------
// Writes transposed [n][k], fp16.
__global__ void prep_w_kernel(const float* __restrict__ kqv_w,
                              const float* __restrict__ kqv_b,
                              const float* __restrict__ a_f,
                              const float* __restrict__ m_f,
                              const float* __restrict__ p_f,
                              const float* __restrict__ a_g,
                              const float* __restrict__ m_g,
                              const float* __restrict__ p_g)
{
    int idx = blockIdx.x * blockDim.x + threadIdx.x;
    if (idx >= Dm * 640) return;
    int n = idx % 640;
    int k = idx / 640;
    float val;
    if (n < 128) {
        val = kqv_w[k * 384 + 128 + n];         // q block
        if (k == 0) g_bbig[n] = kqv_b[128 + n];
    } else {
        int gsel = (n - 128) >> 7;              // 0:kf 1:vf 2:kg 3:vg
        int c = (n - 128) & 127;
        int h = c >> 4, f = c & 15;
        const float* mat; int srcoff; float scale = 1.0f;
        if      (gsel == 0) { mat = a_f; srcoff = 0;   scale = p_f[h] * 0.25f; }
        else if (gsel == 1) { mat = m_f; srcoff = 256; }
        else if (gsel == 2) { mat = a_g; srcoff = 0;   scale = p_g[h] * 0.25f; }
        else                { mat = m_g; srcoff = 256; }
        float s = 0.0f, bs = 0.0f;
        #pragma unroll
        for (int d = 0; d < 16; d++) {
            float w = mat[h * 256 + d * 16 + f];
            s  += kqv_w[k * 384 + srcoff + h * 16 + d] * w;
            bs += kqv_b[srcoff + h * 16 + d] * w;
        }
        val = s * scale;
        if (k == 0) g_bbig[n] = bs * scale;
    }
    g_WbigTh[n * Dm + k] = __float2half_rn(val);
}

// ---------- transpose + fp16-round the other weights --------------------
__global__ void prep2_kernel(const float* __restrict__ out_w,
                             const float* __restrict__ w1,
                             const float* __restrict__ w2)
{
    int idx = blockIdx.x * blockDim.x + threadIdx.x;
    if (idx < 128 * 128) {
        int n = idx >> 7, k = idx & 127;
        g_outwTh[n * 128 + k] = __float2half_rn(out_w[k * 128 + n]);
    }
    idx -= 128 * 128;
    if (idx >= 0 && idx < 512 * 128) {
        int n = idx >> 7, k = idx & 127;          // n in [0,512), k in [0,128)
        g_w1Th[n * 128 + k] = __float2half_rn(w1[k * 512 + n]);
    }
    idx -= 512 * 128;
    if (idx >= 0 && idx < 128 * 512) {
        int n = idx >> 9, k = idx & 511;          // n in [0,128), k in [0,512)
        g_w2Th[n * 512 + k] = __float2half_rn(w2[k * 128 + n]);
    }
}

// ---------------- CSR build: count / scan / scatter ---------------------
__global__ void zero_count_kernel(int N)
{
    int i = blockIdx.x * blockDim.x + threadIdx.x;
    if (i < N) g_count[i] = 0;
}

__global__ void count_kernel(const int* __restrict__ ef,
                             const int* __restrict__ eg, int E)
{
    int i = blockIdx.x * blockDim.x + threadIdx.x;
    if (i >= 2 * E) return;
    int dst = (i < E) ? ef[E + i] : eg[E + (i - E)];
    atomicAdd(&g_count[dst], 1);
}

__global__ void scan_kernel(int N)
{
    __shared__ int sm[1024];
    int t = threadIdx.x;
    int chunk = (N + 1023) >> 10;
    int b0 = t * chunk;
    int b1 = min(b0 + chunk, N);
    int s = 0;
    for (int i = b0; i < b1; i++) s += g_count[i];
    sm[t] = s;
    __syncthreads();
    for (int off = 1; off < 1024; off <<= 1) {
        int v = (t >= off) ? sm[t - off] : 0;
        __syncthreads();
        sm[t] += v;
        __syncthreads();
    }
    int run = sm[t] - s;    // exclusive prefix
    for (int i = b0; i < b1; i++) {
        g_offs[i] = run;
        g_cursor[i] = run;
        run += g_count[i];
    }
    if (t == 1023) g_offs[N] = sm[1023];
}

__global__ void scatter_kernel(const int* __restrict__ ef,
                               const int* __restrict__ eg, int E)
{
    int i = blockIdx.x * blockDim.x + threadIdx.x;
    if (i >= 2 * E) return;
    int src, dst, tbit;
    if (i < E) { src = ef[i];       dst = ef[E + i];       tbit = 0; }
    else       { int j = i - E; src = eg[j]; dst = eg[E + j]; tbit = 1 << 16; }
    int pos = atomicAdd(&g_cursor[dst], 1);
    g_entries[pos] = src | tbit;
}

// ------------- fused segment-softmax + aggregation + GELU ---------------
// 2-wide unrolled: issue both edges' k/v loads before consuming (MLP 4).
__global__ void agg_kernel(int N)
{
    int warp = (blockIdx.x * blockDim.x + threadIdx.x) >> 5;
    int lane = threadIdx.x & 31;
    if (warp >= N) return;
    float4 q4 = *reinterpret_cast<const float4*>(g_q + (size_t)warp * Dm + lane * 4);
    float4 acc = make_float4(0.f, 0.f, 0.f, 0.f);
    float denom = 0.0f;
    int beg = g_offs[warp], end = g_offs[warp + 1];
    int j = beg;
    for (; j + 2 <= end; j += 2) {
        int e0 = g_entries[j];
        int e1 = g_entries[j + 1];
        int s0 = e0 & 0xFFFF, s1 = e1 & 0xFFFF;
        const float* kp0 = (e0 & 0x10000) ? g_kg : g_kf;
        const float* vp0 = (e0 & 0x10000) ? g_vg : g_vf;
        const float* kp1 = (e1 & 0x10000) ? g_kg : g_kf;
        const float* vp1 = (e1 & 0x10000) ? g_vg : g_vf;
        float4 k0 = *reinterpret_cast<const float4*>(kp0 + (size_t)s0 * Dm + lane * 4);
        float4 v0 = *reinterpret_cast<const float4*>(vp0 + (size_t)s0 * Dm + lane * 4);
        float4 k1 = *reinterpret_cast<const float4*>(kp1 + (size_t)s1 * Dm + lane * 4);
        float4 v1 = *reinterpret_cast<const float4*>(vp1 + (size_t)s1 * Dm + lane * 4);
        float p0 = q4.x * k0.x + q4.y * k0.y + q4.z * k0.z + q4.w * k0.w;
        float p1 = q4.x * k1.x + q4.y * k1.y + q4.z * k1.z + q4.w * k1.w;
        p0 += __shfl_xor_sync(0xffffffffu, p0, 1);
        p1 += __shfl_xor_sync(0xffffffffu, p1, 1);
        p0 += __shfl_xor_sync(0xffffffffu, p0, 2);
        p1 += __shfl_xor_sync(0xffffffffu, p1, 2);
        float w0 = __expf(p0);
        float w1 = __expf(p1);
        denom += w0 + w1;
        acc.x += w0 * v0.x + w1 * v1.x;
        acc.y += w0 * v0.y + w1 * v1.y;
        acc.z += w0 * v0.z + w1 * v1.z;
        acc.w += w0 * v0.w + w1 * v1.w;
    }
    for (; j < end; j++) {
        int e   = g_entries[j];
        int src = e & 0xFFFF;
        const float* kp = (e & 0x10000) ? g_kg : g_kf;
        const float* vp = (e & 0x10000) ? g_vg : g_vf;
        float4 k4 = *reinterpret_cast<const float4*>(kp + (size_t)src * Dm + lane * 4);
        float4 v4 = *reinterpret_cast<const float4*>(vp + (size_t)src * Dm + lane * 4);
        float p = q4.x * k4.x + q4.y * k4.y + q4.z * k4.z + q4.w * k4.w;
        p += __shfl_xor_sync(0xffffffffu, p, 1);
        p += __shfl_xor_sync(0xffffffffu, p, 2);
        float w = __expf(p);
        denom += w;
        acc.x += w * v4.x; acc.y += w * v4.y; acc.z += w * v4.z; acc.w += w * v4.w;
    }
    float rd = 1.0f / (denom + 1e-16f);
    float4 o4 = make_float4(gelu_exact(acc.x * rd), gelu_exact(acc.y * rd),
                            gelu_exact(acc.z * rd), gelu_exact(acc.w * rd));
    *reinterpret_cast<float4*>(g_gact + (size_t)warp * Dm + lane * 4) = o4;
}

// =========== fp16 wmma GEMM: C = A[M,K] @ Bt[N,K]^T ======================
// 128x128 CTA tile; 512 threads = 16 warps (4Mx4N), warp tile 32x32 =
// 2x2 wmma m16n16k16 frags, fp32 accumulate. A converted to fp16 at
// staging; weights pre-converted. C tile reuses A/B smem as float buffer.
// MODE 0: A=g_xn,   Bt=g_WbigTh -> {q,kf,vf,kg,vg}(+bbig)  K=128, 5 n-tiles
// MODE 1: A=g_gact, Bt=g_outwTh -> g_x1 = x + sig*(C+b)+(1-sig)*xn  K=128
// MODE 2: A=g_xn2,  Bt=g_w1Th   -> g_hid = gelu(C+b1)      K=128, 4 n-tiles
// MODE 3: A=g_hid,  Bt=g_w2Th   -> out = g_x1 + C + b2     K=512 (4 chunks)
#define APADH 136                          // halves per row (stride)
#define CPAD  132                          // floats per row for C overlay
#define SMEM_BYTES (2 * 128 * APADH * 2)   // 69632 bytes

template <int MODE, int K>
__global__ void __launch_bounds__(512, 1)
wgemm_kernel(const float* __restrict__ bias,
             const float* __restrict__ aux,    // MODE1: x
             const float* __restrict__ skip,   // MODE1 only
             float* __restrict__ outp,         // MODE3: d_out
             int M)
{
    extern __shared__ char smem[];
    __half* sA = reinterpret_cast<__half*>(smem);
    __half* sB = reinterpret_cast<__half*>(smem) + 128 * APADH;
    float*  sC = reinterpret_cast<float*>(smem);

    int tid = threadIdx.x;
    int wid = tid >> 5;
    int m0 = blockIdx.x * 128;
    int n0 = blockIdx.y * 128;

    int wm = (wid & 3) * 32;             // 4 M groups of 32 rows
    int wn = (wid >> 2) * 32;            // 4 N groups of 32 cols

    const float*  A;
    const __half* Bt;
    if      (MODE == 0) { A = g_xn;   Bt = g_WbigTh; }
    else if (MODE == 1) { A = g_gact; Bt = g_outwTh; }
    else if (MODE == 2) { A = g_xn2;  Bt = g_w1Th;   }
    else                { A = g_hid;  Bt = g_w2Th;   }

    wmma::fragment<wmma::accumulator, 16, 16, 16, float> acc[2][2];
    #pragma unroll
    for (int i = 0; i < 2; i++)
        #pragma unroll
        for (int j = 0; j < 2; j++)
            wmma::fill_fragment(acc[i][j], 0.0f);

    for (int kc = 0; kc < K; kc += 128) {
        // ---- stage A (fp32->fp16) and B (fp16 copy); 8 cols per item ----
        #pragma unroll
        for (int i = tid; i < 128 * 16; i += 512) {
            int row = i >> 4, g8 = i & 15;
            int gm = m0 + row;
            float4 v0 = make_float4(0.f, 0.f, 0.f, 0.f);
            float4 v1 = make_float4(0.f, 0.f, 0.f, 0.f);
            if (gm < M) {
                const float* ap = A + (size_t)gm * K + kc + g8 * 8;
                v0 = *reinterpret_cast<const float4*>(ap);
                v1 = *reinterpret_cast<const float4*>(ap + 4);
            }
            __half2 hh[4];
            hh[0] = __floats2half2_rn(v0.x, v0.y);
            hh[1] = __floats2half2_rn(v0.z, v0.w);
            hh[2] = __floats2half2_rn(v1.x, v1.y);
            hh[3] = __floats2half2_rn(v1.z, v1.w);
            *reinterpret_cast<uint4*>(&sA[row * APADH + g8 * 8]) =
                *reinterpret_cast<uint4*>(hh);
            uint4 bv = *reinterpret_cast<const uint4*>(
                Bt + (size_t)(n0 + row) * K + kc + g8 * 8);
            *reinterpret_cast<uint4*>(&sB[row * APADH + g8 * 8]) = bv;
        }
        __syncthreads();

        // ---- 8 k-steps of wmma m16n16k16 ----
        #pragma unroll
        for (int ks = 0; ks < 8; ks++) {
            wmma::fragment<wmma::matrix_a, 16, 16, 16, __half, wmma::row_major> af[2];
            wmma::fragment<wmma::matrix_b, 16, 16, 16, __half, wmma::col_major> bf[2];
            #pragma unroll
            for (int i = 0; i < 2; i++)
                wmma::load_matrix_sync(af[i], &sA[(wm + i * 16) * APADH + ks * 16], APADH);
            #pragma unroll
            for (int j = 0; j < 2; j++)
                wmma::load_matrix_sync(bf[j], &sB[(wn + j * 16) * APADH + ks * 16], APADH);
            #pragma unroll
            for (int i = 0; i < 2; i++)
                #pragma unroll
                for (int j = 0; j < 2; j++)
                    wmma::mma_sync(acc[i][j], af[i], bf[j], acc[i][j]);
        }
        __syncthreads();
    }

    // ---- dump C tile into float overlay, then fused coalesced epilogue --
    #pragma unroll
    for (int i = 0; i < 2; i++)
        #pragma unroll
        for (int j = 0; j < 2; j++)
            wmma::store_matrix_sync(&sC[(wm + i * 16) * CPAD + wn + j * 16],
                                    acc[i][j], CPAD, wmma::mem_row_major);
    __syncthreads();

    float sig = 0.0f;
    if (MODE == 1) sig = 1.0f / (1.0f + __expf(-skip[0]));
    float* Cp = nullptr;
    if (MODE == 0) {
        switch (blockIdx.y) {
            case 0: Cp = g_q;  break;
            case 1: Cp = g_kf; break;
            case 2: Cp = g_vf; break;
            case 3: Cp = g_kg; break;
            default: Cp = g_vg; break;
        }
    }

    #pragma unroll
    for (int i = tid; i < 128 * 32; i += 512) {
        int row = i >> 5, q = i & 31;
        int gm = m0 + row;
        if (gm >= M) continue;
        float4 v = *reinterpret_cast<float4*>(&sC[row * CPAD + q * 4]);
        int gn = n0 + q * 4;
        if (MODE == 0) {
            float4 bb = *reinterpret_cast<const float4*>(g_bbig + gn);
            v.x += bb.x; v.y += bb.y; v.z += bb.z; v.w += bb.w;
            *reinterpret_cast<float4*>(Cp + (size_t)gm * Dm + q * 4) = v;
        } else if (MODE == 1) {
            float4 bb = *reinterpret_cast<const float4*>(bias + gn);
            float4 xv = *reinterpret_cast<const float4*>(aux + (size_t)gm * Dm + gn);
            float4 xn = *reinterpret_cast<const float4*>(g_xn + (size_t)gm * Dm + gn);
            float om = 1.0f - sig;
            v.x = xv.x + sig * (v.x + bb.x) + om * xn.x;
            v.y = xv.y + sig * (v.y + bb.y) + om * xn.y;
            v.z = xv.z + sig * (v.z + bb.z) + om * xn.z;
            v.w = xv.w + sig * (v.w + bb.w) + om * xn.w;
            *reinterpret_cast<float4*>(g_x1 + (size_t)gm * Dm + gn) = v;
        } else if (MODE == 2) {
            float4 bb = *reinterpret_cast<const float4*>(bias + gn);
            v.x = gelu_exact(v.x + bb.x);
            v.y = gelu_exact(v.y + bb.y);
            v.z = gelu_exact(v.z + bb.z);
            v.w = gelu_exact(v.w + bb.w);
            *reinterpret_cast<float4*>(g_hid + (size_t)gm * 512 + gn) = v;
        } else {
            float4 bb = *reinterpret_cast<const float4*>(bias + gn);
            float4 x1 = *reinterpret_cast<const float4*>(g_x1 + (size_t)gm * Dm + gn);
            v.x = x1.x + v.x + bb.x;
            v.y = x1.y + v.y + bb.y;
            v.z = x1.z + v.z + bb.z;
            v.w = x1.w + v.w + bb.w;
            *reinterpret_cast<float4*>(outp + (size_t)gm * Dm + gn) = v;
        }
    }
}

// ------------------------------- launch ---------------------------------
extern "C" void kernel_launch(void* const* d_in, const int* in_sizes, int n_in,
                              void* d_out, int out_size)
{
    const float* x      = (const float*)d_in[0];
    const int*   ef     = (const int*)  d_in[1];
    const int*   eg     = (const int*)  d_in[2];
    const float* kqv_w  = (const float*)d_in[3];
    const float* kqv_b  = (const float*)d_in[4];
    const float* a_f    = (const float*)d_in[5];
    const float* m_f    = (const float*)d_in[6];
    const float* p_f    = (const float*)d_in[7];
    const float* a_g    = (const float*)d_in[8];
    const float* m_g    = (const float*)d_in[9];
    const float* p_g    = (const float*)d_in[10];
    const float* out_w  = (const float*)d_in[11];
    const float* out_b  = (const float*)d_in[12];
    const float* skip   = (const float*)d_in[13];
    const float* ln1_g  = (const float*)d_in[14];
    const float* ln1_b  = (const float*)d_in[15];
    const float* ln2_g  = (const float*)d_in[16];
    const float* ln2_b  = (const float*)d_in[17];
    const float* w1     = (const float*)d_in[18];
    const float* b1     = (const float*)d_in[19];
    const float* w2     = (const float*)d_in[20];
    const float* b2     = (const float*)d_in[21];
    float* out = (float*)d_out;

    int N = in_sizes[0] / Dm;
    int E = in_sizes[1] / 2;
    if (N > NMAX) N = NMAX;
    if (E > EMAX) E = EMAX;

    int mtiles = (N + 127) / 128;

    cudaFuncSetAttribute(wgemm_kernel<0, 128>, cudaFuncAttributeMaxDynamicSharedMemorySize, SMEM_BYTES);
    cudaFuncSetAttribute(wgemm_kernel<1, 128>, cudaFuncAttributeMaxDynamicSharedMemorySize, SMEM_BYTES);
    cudaFuncSetAttribute(wgemm_kernel<2, 128>, cudaFuncAttributeMaxDynamicSharedMemorySize, SMEM_BYTES);
    cudaFuncSetAttribute(wgemm_kernel<3, 512>, cudaFuncAttributeMaxDynamicSharedMemorySize, SMEM_BYTES);

    // 0. LN1: x -> g_xn
    ln_kernel<0><<<(N + 7) / 8, 256>>>(x, ln1_g, ln1_b, N);
    // 1. fold relation matrices into WbigTh/bbig (transposed, fp16)
    prep_w_kernel<<<(Dm * 640 + 255) / 256, 256>>>(kqv_w, kqv_b, a_f, m_f, p_f,
                                                   a_g, m_g, p_g);
    // 2. transpose + convert remaining weights
    prep2_kernel<<<(147456 + 255) / 256, 256>>>(out_w, w1, w2);
    // 3. fused projection GEMM (fp16 wmma): q,kf,vf,kg,vg
    wgemm_kernel<0, 128><<<dim3(mtiles, 5), 512, SMEM_BYTES>>>(
        nullptr, nullptr, nullptr, nullptr, N);
    // 4-7. CSR build by dst
    zero_count_kernel<<<(N + 255) / 256, 256>>>(N);
    count_kernel<<<(2 * E + 255) / 256, 256>>>(ef, eg, E);
    scan_kernel<<<1, 1024>>>(N);
    scatter_kernel<<<(2 * E + 255) / 256, 256>>>(ef, eg, E);
    // 8. fused softmax + aggregation + gelu
    agg_kernel<<<(N + 7) / 8, 256>>>(N);
    // 9. out projection + skip-mix + residual -> g_x1
    wgemm_kernel<1, 128><<<dim3(mtiles, 1), 512, SMEM_BYTES>>>(
        out_b, x, skip, nullptr, N);
    // 10. LN2: g_x1 -> g_xn2
    ln_kernel<1><<<(N + 7) / 8, 256>>>(nullptr, ln2_g, ln2_b, N);
    // 11. FFN up + gelu
    wgemm_kernel<2, 128><<<dim3(mtiles, 4), 512, SMEM_BYTES>>>(
        b1, nullptr, nullptr, nullptr, N);
    // 12. FFN down + residual -> out
    wgemm_kernel<3, 512><<<dim3(mtiles, 1), 512, SMEM_BYTES>>>(
        b2, nullptr, nullptr, out, N);
}

// round 10
// speedup vs baseline: 3.0077x; 1.1381x over previous
#include <cuda_runtime.h>
#include <cuda_fp16.h>
#include <math.h>
#include <stdint.h>
#include <mma.h>

using namespace nvcuda;

// ---------------- problem-size constants (fixed dataset) ----------------
#define NMAX   50000
#define EMAX   300000
#define Dm     128
#define Hh     8
#define DHd    16

// ---------------- scratch (static device memory; no allocations) --------
__device__ float  g_xn  [NMAX * Dm];       // fp32 (MODE1 epilogue)
__device__ __half g_xnh [NMAX * Dm];       // fp16 copy (GEMM A)
__device__ float  g_q   [NMAX * Dm];
__device__ __half g_kv  [NMAX * 512];      // per node: kf|vf|kg|vg (128h each)
__device__ __half g_gacth[NMAX * Dm];
__device__ float  g_x1  [NMAX * Dm];
__device__ __half g_xn2h[NMAX * Dm];
__device__ __half g_hidh[NMAX * 4 * Dm];
__device__ __half g_WbigTh[640 * Dm];      // [n][k] fp16
__device__ __half g_outwTh[Dm * Dm];       // [n][k]
__device__ __half g_w1Th  [512 * Dm];      // [n][k]
__device__ __half g_w2Th  [Dm * 512];      // [n][k]
__device__ float  g_bbig [640];
__device__ int    g_count [NMAX];
__device__ int    g_offs  [NMAX + 1];
__device__ int    g_cursor[NMAX];
__device__ int    g_entries[2 * EMAX];

__device__ __forceinline__ float gelu_exact(float v) {
    return v * 0.5f * (1.0f + erff(v * 0.70710678118654752440f));
}

// ---------------- LayerNorm: one warp per row (128 cols) ----------------
// WHICH 0: x -> g_xn (fp32) + g_xnh (fp16).  WHICH 1: g_x1 -> g_xn2h (fp16).
template <int WHICH>
__global__ void ln_kernel(const float* __restrict__ xin,
                          const float* __restrict__ g,
                          const float* __restrict__ b, int N)
{
    int warp = (blockIdx.x * blockDim.x + threadIdx.x) >> 5;
    int lane = threadIdx.x & 31;
    if (warp >= N) return;
    const float* in = (WHICH == 0) ? xin : g_x1;
    float4 v = *reinterpret_cast<const float4*>(in + (size_t)warp * Dm + lane * 4);
    float s = v.x + v.y + v.z + v.w;
    #pragma unroll
    for (int o = 16; o; o >>= 1) s += __shfl_xor_sync(0xffffffffu, s, o);
    float mu = s * (1.0f / 128.0f);
    float dx = v.x - mu, dy = v.y - mu, dz = v.z - mu, dw = v.w - mu;
    float s2 = dx * dx + dy * dy + dz * dz + dw * dw;
    #pragma unroll
    for (int o = 16; o; o >>= 1) s2 += __shfl_xor_sync(0xffffffffu, s2, o);
    float r = rsqrtf(s2 * (1.0f / 128.0f) + 1e-5f);
    float4 gg = *reinterpret_cast<const float4*>(g + lane * 4);
    float4 bb = *reinterpret_cast<const float4*>(b + lane * 4);
    float4 o4 = make_float4(dx * r * gg.x + bb.x, dy * r * gg.y + bb.y,
                            dz * r * gg.z + bb.z, dw * r * gg.w + bb.w);
    __half2 h0 = __floats2half2_rn(o4.x, o4.y);
    __half2 h1 = __floats2half2_rn(o4.z, o4.w);
    if (WHICH == 0) {
        *reinterpret_cast<float4*>(g_xn + (size_t)warp * Dm + lane * 4) = o4;
        __half2* dst = reinterpret_cast<__half2*>(g_xnh + (size_t)warp * Dm + lane * 4);
        dst[0] = h0; dst[1] = h1;
    } else {
        __half2* dst = reinterpret_cast<__half2*>(g_xn2h + (size_t)warp * Dm + lane * 4);
        dst[0] = h0; dst[1] = h1;
    }
}

// ---------- fold per-head relation matrices into projection weights ------
__global__ void prep_w_kernel(const float* __restrict__ kqv_w,
                              const float* __restrict__ kqv_b,
                              const float* __restrict__ a_f,
                              const float* __restrict__ m_f,
                              const float* __restrict__ p_f,
                              const float* __restrict__ a_g,
                              const float* __restrict__ m_g,
                              const float* __restrict__ p_g)
{
    int idx = blockIdx.x * blockDim.x + threadIdx.x;
    if (idx >= Dm * 640) return;
    int n = idx % 640;
    int k = idx / 640;
    float val;
    if (n < 128) {
        val = kqv_w[k * 384 + 128 + n];         // q block
        if (k == 0) g_bbig[n] = kqv_b[128 + n];
    } else {
        int gsel = (n - 128) >> 7;              // 0:kf 1:vf 2:kg 3:vg
        int c = (n - 128) & 127;
        int h = c >> 4, f = c & 15;
        const float* mat; int srcoff; float scale = 1.0f;
        if      (gsel == 0) { mat = a_f; srcoff = 0;   scale = p_f[h] * 0.25f; }
        else if (gsel == 1) { mat = m_f; srcoff = 256; }
        else if (gsel == 2) { mat = a_g; srcoff = 0;   scale = p_g[h] * 0.25f; }
        else                { mat = m_g; srcoff = 256; }
        float s = 0.0f, bs = 0.0f;
        #pragma unroll
        for (int d = 0; d < 16; d++) {
            float w = mat[h * 256 + d * 16 + f];
            s  += kqv_w[k * 384 + srcoff + h * 16 + d] * w;
            bs += kqv_b[srcoff + h * 16 + d] * w;
        }
        val = s * scale;
        if (k == 0) g_bbig[n] = bs * scale;
    }
    g_WbigTh[n * Dm + k] = __float2half_rn(val);
}

// ---------- transpose + fp16-round the other weights --------------------
__global__ void prep2_kernel(const float* __restrict__ out_w,
                             const float* __restrict__ w1,
                             const float* __restrict__ w2)
{
    int idx = blockIdx.x * blockDim.x + threadIdx.x;
    if (idx < 128 * 128) {
        int n = idx >> 7, k = idx & 127;
        g_outwTh[n * 128 + k] = __float2half_rn(out_w[k * 128 + n]);
    }
    idx -= 128 * 128;
    if (idx >= 0 && idx < 512 * 128) {
        int n = idx >> 7, k = idx & 127;          // n in [0,512), k in [0,128)
        g_w1Th[n * 128 + k] = __float2half_rn(w1[k * 512 + n]);
    }
    idx -= 512 * 128;
    if (idx >= 0 && idx < 128 * 512) {
        int n = idx >> 9, k = idx & 511;          // n in [0,128), k in [0,512)
        g_w2Th[n * 512 + k] = __float2half_rn(w2[k * 128 + n]);
    }
}

// ---------------- CSR build: count / scan / scatter ---------------------
__global__ void zero_count_kernel(int N)
{
    int i = blockIdx.x * blockDim.x + threadIdx.x;
    if (i < N) g_count[i] = 0;
}

__global__ void count_kernel(const int* __restrict__ ef,
                             const int* __restrict__ eg, int E)
{
    int i = blockIdx.x * blockDim.x + threadIdx.x;
    if (i >= 2 * E) return;
    int dst = (i < E) ? ef[E + i] : eg[E + (i - E)];
    atomicAdd(&g_count[dst], 1);
}

__global__ void scan_kernel(int N)
{
    __shared__ int sm[1024];
    int t = threadIdx.x;
    int chunk = (N + 1023) >> 10;
    int b0 = t * chunk;
    int b1 = min(b0 + chunk, N);
    int s = 0;
    for (int i = b0; i < b1; i++) s += g_count[i];
    sm[t] = s;
    __syncthreads();
    for (int off = 1; off < 1024; off <<= 1) {
        int v = (t >= off) ? sm[t - off] : 0;
        __syncthreads();
        sm[t] += v;
        __syncthreads();
    }
    int run = sm[t] - s;    // exclusive prefix
    for (int i = b0; i < b1; i++) {
        g_offs[i] = run;
        g_cursor[i] = run;
        run += g_count[i];
    }
    if (t == 1023) g_offs[N] = sm[1023];
}

__global__ void scatter_kernel(const int* __restrict__ ef,
                               const int* __restrict__ eg, int E)
{
    int i = blockIdx.x * blockDim.x + threadIdx.x;
    if (i >= 2 * E) return;
    int src, dst, tbit;
    if (i < E) { src = ef[i];       dst = ef[E + i];       tbit = 0; }
    else       { int j = i - E; src = eg[j]; dst = eg[E + j]; tbit = 1 << 17; }
    int pos = atomicAdd(&g_cursor[dst], 1);
    g_entries[pos] = src | tbit;
}

// ------------- fused segment-softmax + aggregation + GELU ---------------
// One warp/node; k,v gathered from packed fp16 g_kv (L2-resident, 51MB).
// Entry bit17 selects follower(0) / following(1) k,v pair.
__global__ void agg_kernel(int N)
{
    int warp = (blockIdx.x * blockDim.x + threadIdx.x) >> 5;
    int lane = threadIdx.x & 31;
    if (warp >= N) return;
    float4 q4 = *reinterpret_cast<const float4*>(g_q + (size_t)warp * Dm + lane * 4);
    float4 acc = make_float4(0.f, 0.f, 0.f, 0.f);
    float denom = 0.0f;
    int beg = g_offs[warp], end = g_offs[warp + 1];
    int j = beg;
    for (; j + 2 <= end; j += 2) {
        int e0 = g_entries[j];
        int e1 = g_entries[j + 1];
        // base = src*512 + type*256;  (e & (1<<17)) ? 256 : 0 == (e >> 9) & 256
        const __half* p0 = g_kv + ((size_t)(e0 & 0x1FFFF) << 9) + ((e0 >> 9) & 256);
        const __half* p1 = g_kv + ((size_t)(e1 & 0x1FFFF) << 9) + ((e1 >> 9) & 256);
        uint2 kr0 = *reinterpret_cast<const uint2*>(p0 + lane * 4);
        uint2 vr0 = *reinterpret_cast<const uint2*>(p0 + 128 + lane * 4);
        uint2 kr1 = *reinterpret_cast<const uint2*>(p1 + lane * 4);
        uint2 vr1 = *reinterpret_cast<const uint2*>(p1 + 128 + lane * 4);
        float2 k0a = __half22float2(*reinterpret_cast<__half2*>(&kr0.x));
        float2 k0b = __half22float2(*reinterpret_cast<__half2*>(&kr0.y));
        float2 k1a = __half22float2(*reinterpret_cast<__half2*>(&kr1.x));
        float2 k1b = __half22float2(*reinterpret_cast<__half2*>(&kr1.y));
        float p0s = q4.x * k0a.x + q4.y * k0a.y + q4.z * k0b.x + q4.w * k0b.y;
        float p1s = q4.x * k1a.x + q4.y * k1a.y + q4.z * k1b.x + q4.w * k1b.y;
        p0s += __shfl_xor_sync(0xffffffffu, p0s, 1);
        p1s += __shfl_xor_sync(0xffffffffu, p1s, 1);
        p0s += __shfl_xor_sync(0xffffffffu, p0s, 2);
        p1s += __shfl_xor_sync(0xffffffffu, p1s, 2);
        float w0 = __expf(p0s);
        float w1 = __expf(p1s);
        denom += w0 + w1;
        float2 v0a = __half22float2(*reinterpret_cast<__half2*>(&vr0.x));
        float2 v0b = __half22float2(*reinterpret_cast<__half2*>(&vr0.y));
        float2 v1a = __half22float2(*reinterpret_cast<__half2*>(&vr1.x));
        float2 v1b = __half22float2(*reinterpret_cast<__half2*>(&vr1.y));
        acc.x += w0 * v0a.x + w1 * v1a.x;
        acc.y += w0 * v0a.y + w1 * v1a.y;
        acc.z += w0 * v0b.x + w1 * v1b.x;
        acc.w += w0 * v0b.y + w1 * v1b.y;
    }
    for (; j < end; j++) {
        int e = g_entries[j];
        const __half* p = g_kv + ((size_t)(e & 0x1FFFF) << 9) + ((e >> 9) & 256);
        uint2 kr = *reinterpret_cast<const uint2*>(p + lane * 4);
        uint2 vr = *reinterpret_cast<const uint2*>(p + 128 + lane * 4);
        float2 ka = __half22float2(*reinterpret_cast<__half2*>(&kr.x));
        float2 kb = __half22float2(*reinterpret_cast<__half2*>(&kr.y));
        float ps = q4.x * ka.x + q4.y * ka.y + q4.z * kb.x + q4.w * kb.y;
        ps += __shfl_xor_sync(0xffffffffu, ps, 1);
        ps += __shfl_xor_sync(0xffffffffu, ps, 2);
        float w = __expf(ps);
        denom += w;
        float2 va = __half22float2(*reinterpret_cast<__half2*>(&vr.x));
        float2 vb = __half22float2(*reinterpret_cast<__half2*>(&vr.y));
        acc.x += w * va.x; acc.y += w * va.y; acc.z += w * vb.x; acc.w += w * vb.y;
    }
    float rd = 1.0f / (denom + 1e-16f);
    __half2 o0 = __floats2half2_rn(gelu_exact(acc.x * rd), gelu_exact(acc.y * rd));
    __half2 o1 = __floats2half2_rn(gelu_exact(acc.z * rd), gelu_exact(acc.w * rd));
    __half2* dst = reinterpret_cast<__half2*>(g_gacth + (size_t)warp * Dm + lane * 4);
    dst[0] = o0; dst[1] = o1;
}

// =========== fp16 wmma GEMM: C = A[M,K] @ Bt[N,K]^T ======================
// 128x128 CTA tile; 512 threads = 16 warps (4Mx4N), warp tile 32x32 =
// 2x2 wmma m16n16k16 frags, fp32 accumulate. A and B both fp16 in global.
// MODE 0: A=g_xnh,  Bt=g_WbigTh -> q(fp32) / packed g_kv(fp16)  K=128, 5 nt
// MODE 1: A=g_gacth,Bt=g_outwTh -> g_x1 = x + sig*(C+b)+(1-sig)*xn  K=128
// MODE 2: A=g_xn2h, Bt=g_w1Th   -> g_hidh = gelu(C+b1) fp16   K=128, 4 nt
// MODE 3: A=g_hidh, Bt=g_w2Th   -> out = g_x1 + C + b2        K=512
#define APADH 136                          // halves per row (stride)
#define CPAD  132                          // floats per row for C overlay
#define SMEM_BYTES (2 * 128 * APADH * 2)   // 69632 bytes

template <int MODE, int K>
__global__ void __launch_bounds__(512, 1)
wgemm_kernel(const float* __restrict__ bias,
             const float* __restrict__ aux,    // MODE1: x
             const float* __restrict__ skip,   // MODE1 only
             float* __restrict__ outp,         // MODE3: d_out
             int M)
{
    extern __shared__ char smem[];
    __half* sA = reinterpret_cast<__half*>(smem);
    __half* sB = reinterpret_cast<__half*>(smem) + 128 * APADH;
    float*  sC = reinterpret_cast<float*>(smem);

    int tid = threadIdx.x;
    int wid = tid >> 5;
    int m0 = blockIdx.x * 128;
    int n0 = blockIdx.y * 128;

    int wm = (wid & 3) * 32;             // 4 M groups of 32 rows
    int wn = (wid >> 2) * 32;            // 4 N groups of 32 cols

    const __half* A;
    const __half* Bt;
    if      (MODE == 0) { A = g_xnh;   Bt = g_WbigTh; }
    else if (MODE == 1) { A = g_gacth; Bt = g_outwTh; }
    else if (MODE == 2) { A = g_xn2h;  Bt = g_w1Th;   }
    else                { A = g_hidh;  Bt = g_w2Th;   }

    wmma::fragment<wmma::accumulator, 16, 16, 16, float> acc[2][2];
    #pragma unroll
    for (int i = 0; i < 2; i++)
        #pragma unroll
        for (int j = 0; j < 2; j++)
            wmma::fill_fragment(acc[i][j], 0.0f);

    for (int kc = 0; kc < K; kc += 128) {
        // ---- stage A and B fp16 tiles (8-half vector copies) ----
        #pragma unroll
        for (int i = tid; i < 128 * 16; i += 512) {
            int row = i >> 4, g8 = i & 15;
            int gm = m0 + row;
            uint4 av = make_uint4(0u, 0u, 0u, 0u);
            if (gm < M)
                av = *reinterpret_cast<const uint4*>(A + (size_t)gm * K + kc + g8 * 8);
            *reinterpret_cast<uint4*>(&sA[row * APADH + g8 * 8]) = av;
            uint4 bv = *reinterpret_cast<const uint4*>(
                Bt + (size_t)(n0 + row) * K + kc + g8 * 8);
            *reinterpret_cast<uint4*>(&sB[row * APADH + g8 * 8]) = bv;
        }
        __syncthreads();

        // ---- 8 k-steps of wmma m16n16k16 ----
        #pragma unroll
        for (int ks = 0; ks < 8; ks++) {
            wmma::fragment<wmma::matrix_a, 16, 16, 16, __half, wmma::row_major> af[2];
            wmma::fragment<wmma::matrix_b, 16, 16, 16, __half, wmma::col_major> bf[2];
            #pragma unroll
            for (int i = 0; i < 2; i++)
                wmma::load_matrix_sync(af[i], &sA[(wm + i * 16) * APADH + ks * 16], APADH);
            #pragma unroll
            for (int j = 0; j < 2; j++)
                wmma::load_matrix_sync(bf[j], &sB[(wn + j * 16) * APADH + ks * 16], APADH);
            #pragma unroll
            for (int i = 0; i < 2; i++)
                #pragma unroll
                for (int j = 0; j < 2; j++)
                    wmma::mma_sync(acc[i][j], af[i], bf[j], acc[i][j]);
        }
        __syncthreads();
    }

    // ---- dump C tile into float overlay, then fused coalesced epilogue --
    #pragma unroll
    for (int i = 0; i < 2; i++)
        #pragma unroll
        for (int j = 0; j < 2; j++)
            wmma::store_matrix_sync(&sC[(wm + i * 16) * CPAD + wn + j * 16],
                                    acc[i][j], CPAD, wmma::mem_row_major);
    __syncthreads();

    float sig = 0.0f;
    if (MODE == 1) sig = 1.0f / (1.0f + __expf(-skip[0]));

    #pragma unroll
    for (int i = tid; i < 128 * 32; i += 512) {
        int row = i >> 5, q = i & 31;
        int gm = m0 + row;
        if (gm >= M) continue;
        float4 v = *reinterpret_cast<float4*>(&sC[row * CPAD + q * 4]);
        int gn = n0 + q * 4;
        if (MODE == 0) {
            float4 bb = *reinterpret_cast<const float4*>(g_bbig + gn);
            v.x += bb.x; v.y += bb.y; v.z += bb.z; v.w += bb.w;
            if (blockIdx.y == 0) {
                *reinterpret_cast<float4*>(g_q + (size_t)gm * Dm + q * 4) = v;
            } else {
                __half2 h0 = __floats2half2_rn(v.x, v.y);
                __half2 h1 = __floats2half2_rn(v.z, v.w);
                __half2* dst = reinterpret_cast<__half2*>(
                    g_kv + ((size_t)gm << 9) + (blockIdx.y - 1) * 128 + q * 4);
                dst[0] = h0; dst[1] = h1;
            }
        } else if (MODE == 1) {
            float4 bb = *reinterpret_cast<const float4*>(bias + gn);
            float4 xv = *reinterpret_cast<const float4*>(aux + (size_t)gm * Dm + gn);
            float4 xn = *reinterpret_cast<const float4*>(g_xn + (size_t)gm * Dm + gn);
            float om = 1.0f - sig;
            v.x = xv.x + sig * (v.x + bb.x) + om * xn.x;
            v.y = xv.y + sig * (v.y + bb.y) + om * xn.y;
            v.z = xv.z + sig * (v.z + bb.z) + om * xn.z;
            v.w = xv.w + sig * (v.w + bb.w) + om * xn.w;
            *reinterpret_cast<float4*>(g_x1 + (size_t)gm * Dm + gn) = v;
        } else if (MODE == 2) {
            float4 bb = *reinterpret_cast<const float4*>(bias + gn);
            __half2 h0 = __floats2half2_rn(gelu_exact(v.x + bb.x), gelu_exact(v.y + bb.y));
            __half2 h1 = __floats2half2_rn(gelu_exact(v.z + bb.z), gelu_exact(v.w + bb.w));
            __half2* dst = reinterpret_cast<__half2*>(
                g_hidh + (size_t)gm * 512 + gn);
            dst[0] = h0; dst[1] = h1;
        } else {
            float4 bb = *reinterpret_cast<const float4*>(bias + gn);
            float4 x1 = *reinterpret_cast<const float4*>(g_x1 + (size_t)gm * Dm + gn);
            v.x = x1.x + v.x + bb.x;
            v.y = x1.y + v.y + bb.y;
            v.z = x1.z + v.z + bb.z;
            v.w = x1.w + v.w + bb.w;
            *reinterpret_cast<float4*>(outp + (size_t)gm * Dm + gn) = v;
        }
    }
}

// ------------------------------- launch ---------------------------------
extern "C" void kernel_launch(void* const* d_in, const int* in_sizes, int n_in,
                              void* d_out, int out_size)
{
    const float* x      = (const float*)d_in[0];
    const int*   ef     = (const int*)  d_in[1];
    const int*   eg     = (const int*)  d_in[2];
    const float* kqv_w  = (const float*)d_in[3];
    const float* kqv_b  = (const float*)d_in[4];
    const float* a_f    = (const float*)d_in[5];
    const float* m_f    = (const float*)d_in[6];
    const float* p_f    = (const float*)d_in[7];
    const float* a_g    = (const float*)d_in[8];
    const float* m_g    = (const float*)d_in[9];
    const float* p_g    = (const float*)d_in[10];
    const float* out_w  = (const float*)d_in[11];
    const float* out_b  = (const float*)d_in[12];
    const float* skip   = (const float*)d_in[13];
    const float* ln1_g  = (const float*)d_in[14];
    const float* ln1_b  = (const float*)d_in[15];
    const float* ln2_g  = (const float*)d_in[16];
    const float* ln2_b  = (const float*)d_in[17];
    const float* w1     = (const float*)d_in[18];
    const float* b1     = (const float*)d_in[19];
    const float* w2     = (const float*)d_in[20];
    const float* b2     = (const float*)d_in[21];
    float* out = (float*)d_out;

    int N = in_sizes[0] / Dm;
    int E = in_sizes[1] / 2;
    if (N > NMAX) N = NMAX;
    if (E > EMAX) E = EMAX;

    int mtiles = (N + 127) / 128;

    cudaFuncSetAttribute(wgemm_kernel<0, 128>, cudaFuncAttributeMaxDynamicSharedMemorySize, SMEM_BYTES);
    cudaFuncSetAttribute(wgemm_kernel<1, 128>, cudaFuncAttributeMaxDynamicSharedMemorySize, SMEM_BYTES);
    cudaFuncSetAttribute(wgemm_kernel<2, 128>, cudaFuncAttributeMaxDynamicSharedMemorySize, SMEM_BYTES);
    cudaFuncSetAttribute(wgemm_kernel<3, 512>, cudaFuncAttributeMaxDynamicSharedMemorySize, SMEM_BYTES);

    // 0. LN1: x -> g_xn + g_xnh
    ln_kernel<0><<<(N + 7) / 8, 256>>>(x, ln1_g, ln1_b, N);
    // 1. fold relation matrices into WbigTh/bbig (transposed, fp16)
    prep_w_kernel<<<(Dm * 640 + 255) / 256, 256>>>(kqv_w, kqv_b, a_f, m_f, p_f,
                                                   a_g, m_g, p_g);
    // 2. transpose + convert remaining weights
    prep2_kernel<<<(147456 + 255) / 256, 256>>>(out_w, w1, w2);
    // 3. fused projection GEMM (fp16 wmma): q + packed kv
    wgemm_kernel<0, 128><<<dim3(mtiles, 5), 512, SMEM_BYTES>>>(
        nullptr, nullptr, nullptr, nullptr, N);
    // 4-7. CSR build by dst
    zero_count_kernel<<<(N + 255) / 256, 256>>>(N);
    count_kernel<<<(2 * E + 255) / 256, 256>>>(ef, eg, E);
    scan_kernel<<<1, 1024>>>(N);
    scatter_kernel<<<(2 * E + 255) / 256, 256>>>(ef, eg, E);
    // 8. fused softmax + aggregation + gelu (L2-resident fp16 gather)
    agg_kernel<<<(N + 7) / 8, 256>>>(N);
    // 9. out projection + skip-mix + residual -> g_x1
    wgemm_kernel<1, 128><<<dim3(mtiles, 1), 512, SMEM_BYTES>>>(
        out_b, x, skip, nullptr, N);
    // 10. LN2: g_x1 -> g_xn2h
    ln_kernel<1><<<(N + 7) / 8, 256>>>(nullptr, ln2_g, ln2_b, N);
    // 11. FFN up + gelu -> g_hidh (fp16)
    wgemm_kernel<2, 128><<<dim3(mtiles, 4), 512, SMEM_BYTES>>>(
        b1, nullptr, nullptr, nullptr, N);
    // 12. FFN down + residual -> out
    wgemm_kernel<3, 512><<<dim3(mtiles, 1), 512, SMEM_BYTES>>>(
        b2, nullptr, nullptr, out, N);
}

// round 11
// speedup vs baseline: 3.0465x; 1.0129x over previous
#include <cuda_runtime.h>
#include <cuda_fp16.h>
#include <math.h>
#include <stdint.h>
#include <mma.h>

using namespace nvcuda;

// ---------------- problem-size constants (fixed dataset) ----------------
#define NMAX   50000
#define EMAX   300000
#define Dm     128
#define Hh     8
#define DHd    16

// ---------------- scratch (static device memory; no allocations) --------
__device__ float  g_xn  [NMAX * Dm];       // fp32 (MODE1 epilogue)
__device__ __half g_xnh [NMAX * Dm];       // fp16 copy (GEMM A)
__device__ float  g_q   [NMAX * Dm];
// g_kv layout per node (512 halves): [f-block 256][g-block 256].
// Within a block, lane l (l=0..31) owns halves [l*8, l*8+8):
//   [0:4) = k cols l*4..l*4+3,  [4:8) = v cols l*4..l*4+3.
__device__ __half g_kv  [NMAX * 512];
__device__ __half g_gacth[NMAX * Dm];
__device__ float  g_x1  [NMAX * Dm];
__device__ __half g_xn2h[NMAX * Dm];
__device__ __half g_hidh[NMAX * 4 * Dm];
__device__ __half g_WbigTh[640 * Dm];      // [n][k] fp16
__device__ __half g_outwTh[Dm * Dm];       // [n][k]
__device__ __half g_w1Th  [512 * Dm];      // [n][k]
__device__ __half g_w2Th  [Dm * 512];      // [n][k]
__device__ float  g_bbig [640];
__device__ int    g_count [NMAX];
__device__ int    g_offs  [NMAX + 1];
__device__ int    g_cursor[NMAX];
__device__ int    g_entries[2 * EMAX];

__device__ __forceinline__ float gelu_exact(float v) {
    return v * 0.5f * (1.0f + erff(v * 0.70710678118654752440f));
}

// ---------------- LayerNorm: one warp per row (128 cols) ----------------
template <int WHICH>
__global__ void ln_kernel(const float* __restrict__ xin,
                          const float* __restrict__ g,
                          const float* __restrict__ b, int N)
{
    int warp = (blockIdx.x * blockDim.x + threadIdx.x) >> 5;
    int lane = threadIdx.x & 31;
    if (warp >= N) return;
    const float* in = (WHICH == 0) ? xin : g_x1;
    float4 v = *reinterpret_cast<const float4*>(in + (size_t)warp * Dm + lane * 4);
    float s = v.x + v.y + v.z + v.w;
    #pragma unroll
    for (int o = 16; o; o >>= 1) s += __shfl_xor_sync(0xffffffffu, s, o);
    float mu = s * (1.0f / 128.0f);
    float dx = v.x - mu, dy = v.y - mu, dz = v.z - mu, dw = v.w - mu;
    float s2 = dx * dx + dy * dy + dz * dz + dw * dw;
    #pragma unroll
    for (int o = 16; o; o >>= 1) s2 += __shfl_xor_sync(0xffffffffu, s2, o);
    float r = rsqrtf(s2 * (1.0f / 128.0f) + 1e-5f);
    float4 gg = *reinterpret_cast<const float4*>(g + lane * 4);
    float4 bb = *reinterpret_cast<const float4*>(b + lane * 4);
    float4 o4 = make_float4(dx * r * gg.x + bb.x, dy * r * gg.y + bb.y,
                            dz * r * gg.z + bb.z, dw * r * gg.w + bb.w);
    __half2 h0 = __floats2half2_rn(o4.x, o4.y);
    __half2 h1 = __floats2half2_rn(o4.z, o4.w);
    if (WHICH == 0) {
        *reinterpret_cast<float4*>(g_xn + (size_t)warp * Dm + lane * 4) = o4;
        __half2* dst = reinterpret_cast<__half2*>(g_xnh + (size_t)warp * Dm + lane * 4);
        dst[0] = h0; dst[1] = h1;
    } else {
        __half2* dst = reinterpret_cast<__half2*>(g_xn2h + (size_t)warp * Dm + lane * 4);
        dst[0] = h0; dst[1] = h1;
    }
}

// ---------- fold per-head relation matrices into projection weights ------
__global__ void prep_w_kernel(const float* __restrict__ kqv_w,
                              const float* __restrict__ kqv_b,
                              const float* __restrict__ a_f,
                              const float* __restrict__ m_f,
                              const float* __restrict__ p_f,
                              const float* __restrict__ a_g,
                              const float* __restrict__ m_g,
                              const float* __restrict__ p_g)
{
    int idx = blockIdx.x * blockDim.x + threadIdx.x;
    if (idx >= Dm * 640) return;
    int n = idx % 640;
    int k = idx / 640;
    float val;
    if (n < 128) {
        val = kqv_w[k * 384 + 128 + n];         // q block
        if (k == 0) g_bbig[n] = kqv_b[128 + n];
    } else {
        int gsel = (n - 128) >> 7;              // 0:kf 1:vf 2:kg 3:vg
        int c = (n - 128) & 127;
        int h = c >> 4, f = c & 15;
        const float* mat; int srcoff; float scale = 1.0f;
        if      (gsel == 0) { mat = a_f; srcoff = 0;   scale = p_f[h] * 0.25f; }
        else if (gsel == 1) { mat = m_f; srcoff = 256; }
        else if (gsel == 2) { mat = a_g; srcoff = 0;   scale = p_g[h] * 0.25f; }
        else                { mat = m_g; srcoff = 256; }
        float s = 0.0f, bs = 0.0f;
        #pragma unroll
        for (int d = 0; d < 16; d++) {
            float w = mat[h * 256 + d * 16 + f];
            s  += kqv_w[k * 384 + srcoff + h * 16 + d] * w;
            bs += kqv_b[srcoff + h * 16 + d] * w;
        }
        val = s * scale;
        if (k == 0) g_bbig[n] = bs * scale;
    }
    g_WbigTh[n * Dm + k] = __float2half_rn(val);
}

// ---------- transpose + fp16-round the other weights --------------------
__global__ void prep2_kernel(const float* __restrict__ out_w,
                             const float* __restrict__ w1,
                             const float* __restrict__ w2)
{
    int idx = blockIdx.x * blockDim.x + threadIdx.x;
    if (idx < 128 * 128) {
        int n = idx >> 7, k = idx & 127;
        g_outwTh[n * 128 + k] = __float2half_rn(out_w[k * 128 + n]);
    }
    idx -= 128 * 128;
    if (idx >= 0 && idx < 512 * 128) {
        int n = idx >> 7, k = idx & 127;          // n in [0,512), k in [0,128)
        g_w1Th[n * 128 + k] = __float2half_rn(w1[k * 512 + n]);
    }
    idx -= 512 * 128;
    if (idx >= 0 && idx < 128 * 512) {
        int n = idx >> 9, k = idx & 511;          // n in [0,128), k in [0,512)
        g_w2Th[n * 512 + k] = __float2half_rn(w2[k * 128 + n]);
    }
}

// ---------------- CSR build: count / scan / scatter ---------------------
__global__ void zero_count_kernel(int N)
{
    int i = blockIdx.x * blockDim.x + threadIdx.x;
    if (i < N) g_count[i] = 0;
}

__global__ void count_kernel(const int* __restrict__ ef,
                             const int* __restrict__ eg, int E)
{
    int i = blockIdx.x * blockDim.x + threadIdx.x;
    if (i >= 2 * E) return;
    int dst = (i < E) ? ef[E + i] : eg[E + (i - E)];
    atomicAdd(&g_count[dst], 1);
}

__global__ void scan_kernel(int N)
{
    __shared__ int sm[1024];
    int t = threadIdx.x;
    int chunk = (N + 1023) >> 10;
    int b0 = t * chunk;
    int b1 = min(b0 + chunk, N);
    int s = 0;
    for (int i = b0; i < b1; i++) s += g_count[i];
    sm[t] = s;
    __syncthreads();
    for (int off = 1; off < 1024; off <<= 1) {
        int v = (t >= off) ? sm[t - off] : 0;
        __syncthreads();
        sm[t] += v;
        __syncthreads();
    }
    int run = sm[t] - s;    // exclusive prefix
    for (int i = b0; i < b1; i++) {
        g_offs[i] = run;
        g_cursor[i] = run;
        run += g_count[i];
    }
    if (t == 1023) g_offs[N] = sm[1023];
}

__global__ void scatter_kernel(const int* __restrict__ ef,
                               const int* __restrict__ eg, int E)
{
    int i = blockIdx.x * blockDim.x + threadIdx.x;
    if (i >= 2 * E) return;
    int src, dst, tbit;
    if (i < E) { src = ef[i];       dst = ef[E + i];       tbit = 0; }
    else       { int j = i - E; src = eg[j]; dst = eg[E + j]; tbit = 1 << 17; }
    int pos = atomicAdd(&g_cursor[dst], 1);
    g_entries[pos] = src | tbit;
}

// ------------- fused segment-softmax + aggregation + GELU ---------------
// One warp/node. Per edge ONE uint4 load per lane (interleaved k|v layout),
// 4-deep unroll -> 4 outstanding 16B loads per warp.
__global__ void agg_kernel(int N)
{
    int warp = (blockIdx.x * blockDim.x + threadIdx.x) >> 5;
    int lane = threadIdx.x & 31;
    if (warp >= N) return;
    float4 q4 = *reinterpret_cast<const float4*>(g_q + (size_t)warp * Dm + lane * 4);
    float4 acc = make_float4(0.f, 0.f, 0.f, 0.f);
    float denom = 0.0f;
    int beg = g_offs[warp], end = g_offs[warp + 1];
    int j = beg;
    int loff = lane * 8;
    for (; j + 4 <= end; j += 4) {
        uint4 r[4];
        #pragma unroll
        for (int u = 0; u < 4; u++) {
            int e = g_entries[j + u];
            const __half* p = g_kv + ((size_t)(e & 0x1FFFF) << 9)
                                   + ((e >> 9) & 256) + loff;
            r[u] = *reinterpret_cast<const uint4*>(p);
        }
        float ps[4];
        #pragma unroll
        for (int u = 0; u < 4; u++) {
            float2 ka = __half22float2(*reinterpret_cast<__half2*>(&r[u].x));
            float2 kb = __half22float2(*reinterpret_cast<__half2*>(&r[u].y));
            ps[u] = q4.x * ka.x + q4.y * ka.y + q4.z * kb.x + q4.w * kb.y;
        }
        #pragma unroll
        for (int u = 0; u < 4; u++) {
            ps[u] += __shfl_xor_sync(0xffffffffu, ps[u], 1);
            ps[u] += __shfl_xor_sync(0xffffffffu, ps[u], 2);
        }
        #pragma unroll
        for (int u = 0; u < 4; u++) {
            float w = __expf(ps[u]);
            denom += w;
            float2 va = __half22float2(*reinterpret_cast<__half2*>(&r[u].z));
            float2 vb = __half22float2(*reinterpret_cast<__half2*>(&r[u].w));
            acc.x += w * va.x; acc.y += w * va.y;
            acc.z += w * vb.x; acc.w += w * vb.y;
        }
    }
    for (; j < end; j++) {
        int e = g_entries[j];
        const __half* p = g_kv + ((size_t)(e & 0x1FFFF) << 9)
                               + ((e >> 9) & 256) + loff;
        uint4 r = *reinterpret_cast<const uint4*>(p);
        float2 ka = __half22float2(*reinterpret_cast<__half2*>(&r.x));
        float2 kb = __half22float2(*reinterpret_cast<__half2*>(&r.y));
        float ps = q4.x * ka.x + q4.y * ka.y + q4.z * kb.x + q4.w * kb.y;
        ps += __shfl_xor_sync(0xffffffffu, ps, 1);
        ps += __shfl_xor_sync(0xffffffffu, ps, 2);
        float w = __expf(ps);
        denom += w;
        float2 va = __half22float2(*reinterpret_cast<__half2*>(&r.z));
        float2 vb = __half22float2(*reinterpret_cast<__half2*>(&r.w));
        acc.x += w * va.x; acc.y += w * va.y;
        acc.z += w * vb.x; acc.w += w * vb.y;
    }
    float rd = 1.0f / (denom + 1e-16f);
    __half2 o0 = __floats2half2_rn(gelu_exact(acc.x * rd), gelu_exact(acc.y * rd));
    __half2 o1 = __floats2half2_rn(gelu_exact(acc.z * rd), gelu_exact(acc.w * rd));
    __half2* dst = reinterpret_cast<__half2*>(g_gacth + (size_t)warp * Dm + lane * 4);
    dst[0] = o0; dst[1] = o1;
}

// =========== fp16 wmma GEMM: C = A[M,K] @ Bt[N,K]^T ======================
// 128x128 CTA tile; 256 threads = 8 warps (2Mx4N), warp tile 64x32 =
// 4x2 wmma m16n16k16 frags, fp32 accumulate. 2 CTAs/SM -> staging of one
// CTA overlaps MMA of the other.
// MODE 0: A=g_xnh,  Bt=g_WbigTh -> q(fp32) / interleaved g_kv  K=128, 5 nt
// MODE 1: A=g_gacth,Bt=g_outwTh -> g_x1 = x + sig*(C+b)+(1-sig)*xn  K=128
// MODE 2: A=g_xn2h, Bt=g_w1Th   -> g_hidh = gelu(C+b1) fp16   K=128, 4 nt
// MODE 3: A=g_hidh, Bt=g_w2Th   -> out = g_x1 + C + b2        K=512
#define APADH 136                          // halves per row (stride)
#define CPAD  132                          // floats per row for C overlay
#define SMEM_BYTES (2 * 128 * APADH * 2)   // 69632 bytes

template <int MODE, int K>
__global__ void __launch_bounds__(256, 2)
wgemm_kernel(const float* __restrict__ bias,
             const float* __restrict__ aux,    // MODE1: x
             const float* __restrict__ skip,   // MODE1 only
             float* __restrict__ outp,         // MODE3: d_out
             int M)
{
    extern __shared__ char smem[];
    __half* sA = reinterpret_cast<__half*>(smem);
    __half* sB = reinterpret_cast<__half*>(smem) + 128 * APADH;
    float*  sC = reinterpret_cast<float*>(smem);

    int tid = threadIdx.x;
    int wid = tid >> 5;
    int m0 = blockIdx.x * 128;
    int n0 = blockIdx.y * 128;

    int wm = (wid & 1) * 64;             // 2 M groups of 64 rows
    int wn = (wid >> 1) * 32;            // 4 N groups of 32 cols

    const __half* A;
    const __half* Bt;
    if      (MODE == 0) { A = g_xnh;   Bt = g_WbigTh; }
    else if (MODE == 1) { A = g_gacth; Bt = g_outwTh; }
    else if (MODE == 2) { A = g_xn2h;  Bt = g_w1Th;   }
    else                { A = g_hidh;  Bt = g_w2Th;   }

    wmma::fragment<wmma::accumulator, 16, 16, 16, float> acc[4][2];
    #pragma unroll
    for (int i = 0; i < 4; i++)
        #pragma unroll
        for (int j = 0; j < 2; j++)
            wmma::fill_fragment(acc[i][j], 0.0f);

    for (int kc = 0; kc < K; kc += 128) {
        // ---- stage A and B fp16 tiles (8-half vector copies) ----
        #pragma unroll
        for (int i = tid; i < 128 * 16; i += 256) {
            int row = i >> 4, g8 = i & 15;
            int gm = m0 + row;
            uint4 av = make_uint4(0u, 0u, 0u, 0u);
            if (gm < M)
                av = *reinterpret_cast<const uint4*>(A + (size_t)gm * K + kc + g8 * 8);
            *reinterpret_cast<uint4*>(&sA[row * APADH + g8 * 8]) = av;
            uint4 bv = *reinterpret_cast<const uint4*>(
                Bt + (size_t)(n0 + row) * K + kc + g8 * 8);
            *reinterpret_cast<uint4*>(&sB[row * APADH + g8 * 8]) = bv;
        }
        __syncthreads();

        // ---- 8 k-steps of wmma m16n16k16 (B first, A streamed) ----
        #pragma unroll
        for (int ks = 0; ks < 8; ks++) {
            wmma::fragment<wmma::matrix_b, 16, 16, 16, __half, wmma::col_major> bf[2];
            #pragma unroll
            for (int j = 0; j < 2; j++)
                wmma::load_matrix_sync(bf[j], &sB[(wn + j * 16) * APADH + ks * 16], APADH);
            #pragma unroll
            for (int i = 0; i < 4; i++) {
                wmma::fragment<wmma::matrix_a, 16, 16, 16, __half, wmma::row_major> af;
                wmma::load_matrix_sync(af, &sA[(wm + i * 16) * APADH + ks * 16], APADH);
                wmma::mma_sync(acc[i][0], af, bf[0], acc[i][0]);
                wmma::mma_sync(acc[i][1], af, bf[1], acc[i][1]);
            }
        }
        __syncthreads();
    }

    // ---- dump C tile into float overlay, then fused coalesced epilogue --
    #pragma unroll
    for (int i = 0; i < 4; i++)
        #pragma unroll
        for (int j = 0; j < 2; j++)
            wmma::store_matrix_sync(&sC[(wm + i * 16) * CPAD + wn + j * 16],
                                    acc[i][j], CPAD, wmma::mem_row_major);
    __syncthreads();

    float sig = 0.0f;
    if (MODE == 1) sig = 1.0f / (1.0f + __expf(-skip[0]));

    #pragma unroll
    for (int i = tid; i < 128 * 32; i += 256) {
        int row = i >> 5, q = i & 31;
        int gm = m0 + row;
        if (gm >= M) continue;
        float4 v = *reinterpret_cast<float4*>(&sC[row * CPAD + q * 4]);
        int gn = n0 + q * 4;
        if (MODE == 0) {
            float4 bb = *reinterpret_cast<const float4*>(g_bbig + gn);
            v.x += bb.x; v.y += bb.y; v.z += bb.z; v.w += bb.w;
            if (blockIdx.y == 0) {
                *reinterpret_cast<float4*>(g_q + (size_t)gm * Dm + q * 4) = v;
            } else {
                // interleaved kv layout: type 0..3 = kf,vf,kg,vg
                int type = blockIdx.y - 1;
                int tb = (type >> 1) * 256;     // f or g block
                int koff = (type & 1) * 4;      // k at +0, v at +4
                __half2 h0 = __floats2half2_rn(v.x, v.y);
                __half2 h1 = __floats2half2_rn(v.z, v.w);
                __half* base = g_kv + ((size_t)gm << 9) + tb + q * 8 + koff;
                *reinterpret_cast<__half2*>(base) = h0;
                *reinterpret_cast<__half2*>(base + 2) = h1;
            }
        } else if (MODE == 1) {
            float4 bb = *reinterpret_cast<const float4*>(bias + gn);
            float4 xv = *reinterpret_cast<const float4*>(aux + (size_t)gm * Dm + gn);
            float4 xn = *reinterpret_cast<const float4*>(g_xn + (size_t)gm * Dm + gn);
            float om = 1.0f - sig;
            v.x = xv.x + sig * (v.x + bb.x) + om * xn.x;
            v.y = xv.y + sig * (v.y + bb.y) + om * xn.y;
            v.z = xv.z + sig * (v.z + bb.z) + om * xn.z;
            v.w = xv.w + sig * (v.w + bb.w) + om * xn.w;
            *reinterpret_cast<float4*>(g_x1 + (size_t)gm * Dm + gn) = v;
        } else if (MODE == 2) {
            float4 bb = *reinterpret_cast<const float4*>(bias + gn);
            __half2 h0 = __floats2half2_rn(gelu_exact(v.x + bb.x), gelu_exact(v.y + bb.y));
            __half2 h1 = __floats2half2_rn(gelu_exact(v.z + bb.z), gelu_exact(v.w + bb.w));
            __half2* dst = reinterpret_cast<__half2*>(
                g_hidh + (size_t)gm * 512 + gn);
            dst[0] = h0; dst[1] = h1;
        } else {
            float4 bb = *reinterpret_cast<const float4*>(bias + gn);
            float4 x1 = *reinterpret_cast<const float4*>(g_x1 + (size_t)gm * Dm + gn);
            v.x = x1.x + v.x + bb.x;
            v.y = x1.y + v.y + bb.y;
            v.z = x1.z + v.z + bb.z;
            v.w = x1.w + v.w + bb.w;
            *reinterpret_cast<float4*>(outp + (size_t)gm * Dm + gn) = v;
        }
    }
}

// ------------------------------- launch ---------------------------------
extern "C" void kernel_launch(void* const* d_in, const int* in_sizes, int n_in,
                              void* d_out, int out_size)
{
    const float* x      = (const float*)d_in[0];
    const int*   ef     = (const int*)  d_in[1];
    const int*   eg     = (const int*)  d_in[2];
    const float* kqv_w  = (const float*)d_in[3];
    const float* kqv_b  = (const float*)d_in[4];
    const float* a_f    = (const float*)d_in[5];
    const float* m_f    = (const float*)d_in[6];
    const float* p_f    = (const float*)d_in[7];
    const float* a_g    = (const float*)d_in[8];
    const float* m_g    = (const float*)d_in[9];
    const float* p_g    = (const float*)d_in[10];
    const float* out_w  = (const float*)d_in[11];
    const float* out_b  = (const float*)d_in[12];
    const float* skip   = (const float*)d_in[13];
    const float* ln1_g  = (const float*)d_in[14];
    const float* ln1_b  = (const float*)d_in[15];
    const float* ln2_g  = (const float*)d_in[16];
    const float* ln2_b  = (const float*)d_in[17];
    const float* w1     = (const float*)d_in[18];
    const float* b1     = (const float*)d_in[19];
    const float* w2     = (const float*)d_in[20];
    const float* b2     = (const float*)d_in[21];
    float* out = (float*)d_out;

    int N = in_sizes[0] / Dm;
    int E = in_sizes[1] / 2;
    if (N > NMAX) N = NMAX;
    if (E > EMAX) E = EMAX;

    int mtiles = (N + 127) / 128;

    cudaFuncSetAttribute(wgemm_kernel<0, 128>, cudaFuncAttributeMaxDynamicSharedMemorySize, SMEM_BYTES);
    cudaFuncSetAttribute(wgemm_kernel<1, 128>, cudaFuncAttributeMaxDynamicSharedMemorySize, SMEM_BYTES);
    cudaFuncSetAttribute(wgemm_kernel<2, 128>, cudaFuncAttributeMaxDynamicSharedMemorySize, SMEM_BYTES);
    cudaFuncSetAttribute(wgemm_kernel<3, 512>, cudaFuncAttributeMaxDynamicSharedMemorySize, SMEM_BYTES);

    // 0. LN1: x -> g_xn + g_xnh
    ln_kernel<0><<<(N + 7) / 8, 256>>>(x, ln1_g, ln1_b, N);
    // 1. fold relation matrices into WbigTh/bbig (transposed, fp16)
    prep_w_kernel<<<(Dm * 640 + 255) / 256, 256>>>(kqv_w, kqv_b, a_f, m_f, p_f,
                                                   a_g, m_g, p_g);
    // 2. transpose + convert remaining weights
    prep2_kernel<<<(147456 + 255) / 256, 256>>>(out_w, w1, w2);
    // 3. fused projection GEMM (fp16 wmma): q + interleaved kv
    wgemm_kernel<0, 128><<<dim3(mtiles, 5), 256, SMEM_BYTES>>>(
        nullptr, nullptr, nullptr, nullptr, N);
    // 4-7. CSR build by dst
    zero_count_kernel<<<(N + 255) / 256, 256>>>(N);
    count_kernel<<<(2 * E + 255) / 256, 256>>>(ef, eg, E);
    scan_kernel<<<1, 1024>>>(N);
    scatter_kernel<<<(2 * E + 255) / 256, 256>>>(ef, eg, E);
    // 8. fused softmax + aggregation + gelu (1 uint4/edge gather)
    agg_kernel<<<(N + 7) / 8, 256>>>(N);
    // 9. out projection + skip-mix + residual -> g_x1
    wgemm_kernel<1, 128><<<dim3(mtiles, 1), 256, SMEM_BYTES>>>(
        out_b, x, skip, nullptr, N);
    // 10. LN2: g_x1 -> g_xn2h
    ln_kernel<1><<<(N + 7) / 8, 256>>>(nullptr, ln2_g, ln2_b, N);
    // 11. FFN up + gelu -> g_hidh (fp16)
    wgemm_kernel<2, 128><<<dim3(mtiles, 4), 256, SMEM_BYTES>>>(
        b1, nullptr, nullptr, nullptr, N);
    // 12. FFN down + residual -> out
    wgemm_kernel<3, 512><<<dim3(mtiles, 1), 256, SMEM_BYTES>>>(
        b2, nullptr, nullptr, out, N);
}